// round 15
// baseline (speedup 1.0000x reference)
#include <cuda_runtime.h>
#include <cuda_bf16.h>
#include <math_constants.h>
#include <cstdint>

#define NB    256
#define NPG   512
#define NGN   131072
#define EGE   1048576
#define NQPG  16
#define NQN   4096
#define EQE   32768
#define FIN   64
#define HD    128
#define NL    2

typedef __nv_bfloat16 bf16;
typedef __nv_bfloat162 bf162;

#define OFF_WG  0
#define OFF_WQ  8192
#define OFF_W1(l) (16384 + (l) * 32768)
#define OFF_W2(l) (16384 + (l) * 32768 + 16384)
#define WTOT    (16384 + NL * 32768)

// ---------------- device scratch ----------------
__device__ __align__(16) float d_hgA[NGN * HD];
__device__ __align__(16) float d_hgB[NGN * HD];
__device__ __align__(16) float d_hqA[NQN * HD];
__device__ __align__(16) float d_hqB[NQN * HD];
__device__ float d_ssqgA[NGN];
__device__ float d_ssqgB[NGN];
__device__ float d_ssqqA[NQN];
__device__ float d_ssqqB[NQN];
__device__ float d_invg[NGN];
__device__ float d_ssqa0[NB];
__device__ float d_ssqa1[NB];
__device__ float d_vg0[NB * HD];
__device__ float d_vg1[NB * HD];
__device__ float d_part[(NGN / 128) * HD];
__device__ __align__(16) bf16 d_Wh[WTOT];
__device__ __align__(16) bf16 d_Wl[WTOT];
__device__ int d_csrg[EGE];      // stores SRC node index per CSR slot
__device__ int d_startg[NGN];
__device__ int d_cntg[NGN];
__device__ int d_csrq[EQE];
__device__ int d_startq[NQN];
__device__ int d_cntq[NQN];

// ---------------- helpers ----------------
__device__ __forceinline__ uint32_t sptr(const void* p) {
    return (uint32_t)__cvta_generic_to_shared(p);
}
__device__ __forceinline__ void ldsm4(uint32_t& r0, uint32_t& r1, uint32_t& r2, uint32_t& r3, uint32_t a) {
    asm volatile("ldmatrix.sync.aligned.m8n8.x4.shared.b16 {%0,%1,%2,%3},[%4];\n"
                 : "=r"(r0), "=r"(r1), "=r"(r2), "=r"(r3) : "r"(a));
}
__device__ __forceinline__ void ldsm4t(uint32_t& r0, uint32_t& r1, uint32_t& r2, uint32_t& r3, uint32_t a) {
    asm volatile("ldmatrix.sync.aligned.m8n8.x4.trans.shared.b16 {%0,%1,%2,%3},[%4];\n"
                 : "=r"(r0), "=r"(r1), "=r"(r2), "=r"(r3) : "r"(a));
}
__device__ __forceinline__ void mma16816(float* c, const uint32_t* a, uint32_t b0, uint32_t b1) {
    asm volatile("mma.sync.aligned.m16n8k16.row.col.f32.bf16.bf16.f32 "
                 "{%0,%1,%2,%3},{%4,%5,%6,%7},{%8,%9},{%0,%1,%2,%3};\n"
                 : "+f"(c[0]), "+f"(c[1]), "+f"(c[2]), "+f"(c[3])
                 : "r"(a[0]), "r"(a[1]), "r"(a[2]), "r"(a[3]), "r"(b0), "r"(b1));
}
__device__ __forceinline__ void cpa16(void* s, const void* g) {
    asm volatile("cp.async.cg.shared.global [%0], [%1], 16;\n" :: "r"(sptr(s)), "l"(g));
}
__device__ __forceinline__ void cpcommit() { asm volatile("cp.async.commit_group;\n"); }
template<int N> __device__ __forceinline__ void cpwait() {
    asm volatile("cp.async.wait_group %0;\n" :: "n"(N));
}
__device__ __forceinline__ void split_store(bf16* hi, bf16* lo, float x, float y) {
    bf162 h = __floats2bfloat162_rn(x, y);
    bf162 l = __floats2bfloat162_rn(x - __bfloat162float(h.x), y - __bfloat162float(h.y));
    *(bf162*)hi = h;
    *(bf162*)lo = l;
}
__device__ __forceinline__ float quadsum(float v) {
    v += __shfl_xor_sync(0xffffffffu, v, 1);
    v += __shfl_xor_sync(0xffffffffu, v, 2);
    return v;
}

// ---------------- O(E) deterministic CSR build (stores src idx, parallel scan) ----------------
template<int NPGT, int EPGT, int W>
__global__ void build_csr3(const int* __restrict__ src, const int* __restrict__ dst,
                           int* __restrict__ csr_src,
                           int* __restrict__ start,
                           int* __restrict__ cnt)
{
    __shared__ int hw[W][NPGT];
    __shared__ int wsum[32];
    const int g = blockIdx.x;
    const int nodebase = g * NPGT, edgebase = g * EPGT;
    const int tid = threadIdx.x, w = tid >> 5, lane = tid & 31;
    const int EPW = EPGT / W;

    for (int i = tid; i < W * NPGT; i += W * 32) ((int*)hw)[i] = 0;
    __syncthreads();

    const int ebase = edgebase + w * EPW;
    for (int c0 = 0; c0 < EPW; c0 += 32) {
        int d = dst[ebase + c0 + lane] - nodebase;
        unsigned mm = __match_any_sync(0xffffffffu, d);
        int leader = __ffs(mm) - 1;
        if (lane == leader) atomicAdd(&hw[w][d], __popc(mm));
    }
    __syncthreads();

    int deg = 0, excl = 0;
    if (tid < NPGT) {
        #pragma unroll
        for (int ww = 0; ww < W; ww++) deg += hw[ww][tid];
        cnt[nodebase + tid] = deg;
    }
    if constexpr (NPGT >= 64) {
        int inc = deg;
        #pragma unroll
        for (int o = 1; o < 32; o <<= 1) {
            int n = __shfl_up_sync(0xffffffffu, inc, o);
            if (lane >= o) inc += n;
        }
        if (lane == 31) wsum[w] = inc;
        __syncthreads();
        if (tid < 32) {
            int s = (tid < NPGT / 32) ? wsum[tid] : 0;
            #pragma unroll
            for (int o = 1; o < 32; o <<= 1) {
                int n = __shfl_up_sync(0xffffffffu, s, o);
                if (tid >= o) s += n;
            }
            if (tid < NPGT / 32) wsum[tid] = s;
        }
        __syncthreads();
        excl = inc - deg + (w ? wsum[w - 1] : 0);
    } else {
        __shared__ int soff[NPGT];
        if (tid < NPGT) soff[tid] = deg;
        __syncthreads();
        if (tid == 0) {
            int run = 0;
            for (int i = 0; i < NPGT; i++) { int d0 = soff[i]; soff[i] = run; run += d0; }
        }
        __syncthreads();
        if (tid < NPGT) excl = soff[tid];
    }
    __syncthreads();
    if (tid < NPGT) {
        int run = edgebase + excl;
        start[nodebase + tid] = run;
        #pragma unroll
        for (int ww = 0; ww < W; ww++) { int t0 = hw[ww][tid]; hw[ww][tid] = run; run += t0; }
    }
    __syncthreads();

    for (int c0 = 0; c0 < EPW; c0 += 32) {
        int e = ebase + c0 + lane;
        int d = dst[e] - nodebase;
        int sv = src[e];
        unsigned mm = __match_any_sync(0xffffffffu, d);
        int leader = __ffs(mm) - 1;
        int r = __popc(mm & ((1u << lane) - 1));
        int basepos = 0;
        if (lane == leader) { basepos = hw[w][d]; hw[w][d] += __popc(mm); }
        basepos = __shfl_sync(0xffffffffu, basepos, leader);
        csr_src[basepos + r] = sv;
    }
}

// ---------------- merged: query CSR build + weight split (block-range branch) ----------------
__global__ void setup_q_ws(const int* __restrict__ qsrc, const int* __restrict__ qdst,
                           int* __restrict__ csrq, int* __restrict__ startq, int* __restrict__ cntq,
                           const float* __restrict__ Wg, const float* __restrict__ Wq,
                           const float* __restrict__ W1r, const float* __restrict__ W2r,
                           bf16* __restrict__ Wh, bf16* __restrict__ Wl)
{
    if ((int)blockIdx.x < NB) {
        constexpr int NPGT = NQPG, EPGT = EQE / NB, W = 4;
        __shared__ int hw[W][NPGT];
        __shared__ int soff[NPGT];
        const int g = blockIdx.x;
        const int nodebase = g * NPGT, edgebase = g * EPGT;
        const int tid = threadIdx.x, w = tid >> 5, lane = tid & 31;
        const int EPW = EPGT / W;

        for (int i = tid; i < W * NPGT; i += 128) ((int*)hw)[i] = 0;
        __syncthreads();

        const int ebase = edgebase + w * EPW;
        for (int c0 = 0; c0 < EPW; c0 += 32) {
            int d = qdst[ebase + c0 + lane] - nodebase;
            unsigned mm = __match_any_sync(0xffffffffu, d);
            int leader = __ffs(mm) - 1;
            if (lane == leader) atomicAdd(&hw[w][d], __popc(mm));
        }
        __syncthreads();

        int deg = 0;
        if (tid < NPGT) {
            #pragma unroll
            for (int ww = 0; ww < W; ww++) deg += hw[ww][tid];
            cntq[nodebase + tid] = deg;
            soff[tid] = deg;
        }
        __syncthreads();
        if (tid == 0) {
            int run = 0;
            for (int i = 0; i < NPGT; i++) { int d0 = soff[i]; soff[i] = run; run += d0; }
        }
        __syncthreads();
        if (tid < NPGT) {
            int run = edgebase + soff[tid];
            startq[nodebase + tid] = run;
            #pragma unroll
            for (int ww = 0; ww < W; ww++) { int t0 = hw[ww][tid]; hw[ww][tid] = run; run += t0; }
        }
        __syncthreads();

        for (int c0 = 0; c0 < EPW; c0 += 32) {
            int e = ebase + c0 + lane;
            int d = qdst[e] - nodebase;
            int sv = qsrc[e];
            unsigned mm = __match_any_sync(0xffffffffu, d);
            int leader = __ffs(mm) - 1;
            int r = __popc(mm & ((1u << lane) - 1));
            int basepos = 0;
            if (lane == leader) { basepos = hw[w][d]; hw[w][d] += __popc(mm); }
            basepos = __shfl_sync(0xffffffffu, basepos, leader);
            csrq[basepos + r] = sv;
        }
    } else {
        int i4 = ((int)blockIdx.x - NB) * 128 + threadIdx.x;
        int e0 = i4 * 4;
        if (e0 >= WTOT) return;
        const float* src;
        if (e0 < 8192) src = Wg + e0;
        else if (e0 < 16384) src = Wq + (e0 - 8192);
        else {
            int t = e0 - 16384;
            int l = t / 32768, r = t % 32768;
            if (r < 16384) src = W1r + (size_t)l * 32768 + r;
            else           src = W2r + (size_t)l * 16384 + (r - 16384);
        }
        float4 v = *(const float4*)src;
        split_store(Wh + e0,     Wl + e0,     v.x, v.y);
        split_store(Wh + e0 + 2, Wl + e0 + 2, v.z, v.w);
    }
}

// ---------------- merged input projection GEMM (K=64, two operand sets) ----------------
__global__ __launch_bounds__(256, 2) void gemm_in(
    const float* __restrict__ A0, const bf16* __restrict__ Bh0, const bf16* __restrict__ Bl0,
    const float* __restrict__ bias0, float* __restrict__ C0, float* __restrict__ ssq0,
    const float* __restrict__ A1, const bf16* __restrict__ Bh1, const bf16* __restrict__ Bl1,
    const float* __restrict__ bias1, float* __restrict__ C1, float* __restrict__ ssq1,
    int nb0)
{
    extern __shared__ __align__(16) char sm[];
    bf16* sAh = (bf16*)sm;
    bf16* sAl = sAh + 128 * 72;
    bf16* sBh = sAl + 128 * 72;
    bf16* sBl = sBh + 64 * 136;
    float* sred = (float*)(sBl + 64 * 136);

    int tid = threadIdx.x;
    int wid = tid >> 5, lane = tid & 31;
    int warp_m = wid >> 1, warp_n = wid & 1;

    const float* A; const bf16* Bh; const bf16* Bl; const float* bias;
    float* C; float* ssq_out; int row0;
    if ((int)blockIdx.x < nb0) {
        A = A0; Bh = Bh0; Bl = Bl0; bias = bias0; C = C0; ssq_out = ssq0;
        row0 = blockIdx.x * 128;
    } else {
        A = A1; Bh = Bh1; Bl = Bl1; bias = bias1; C = C1; ssq_out = ssq1;
        row0 = (blockIdx.x - nb0) * 128;
    }

    sred[tid] = 0.0f;

    #pragma unroll
    for (int it = 0; it < 8; it++) {
        int idx = tid + it * 256;
        int m = idx >> 4, f = (idx & 15) * 4;
        float4 v = *(const float4*)(A + (size_t)(row0 + m) * FIN + f);
        split_store(&sAh[m * 72 + f],     &sAl[m * 72 + f],     v.x, v.y);
        split_store(&sAh[m * 72 + f + 2], &sAl[m * 72 + f + 2], v.z, v.w);
    }
    #pragma unroll
    for (int it = 0; it < 4; it++) {
        int idx = tid + it * 256;
        int kk = idx >> 4, f = (idx & 15) * 8;
        *(float4*)(sBh + kk * 136 + f) = *(const float4*)(Bh + kk * 128 + f);
        *(float4*)(sBl + kk * 136 + f) = *(const float4*)(Bl + kk * 128 + f);
    }
    __syncthreads();

    float acc[2][8][4];
    #pragma unroll
    for (int i = 0; i < 2; i++)
        #pragma unroll
        for (int j = 0; j < 8; j++)
            #pragma unroll
            for (int k = 0; k < 4; k++) acc[i][j][k] = 0.0f;

    #pragma unroll
    for (int ks = 0; ks < FIN; ks += 16) {
        uint32_t ah[2][4], al[2][4];
        #pragma unroll
        for (int mt = 0; mt < 2; mt++) {
            int r = warp_m * 32 + mt * 16 + (lane & 15);
            int c = ks + (lane >> 4) * 8;
            ldsm4(ah[mt][0], ah[mt][1], ah[mt][2], ah[mt][3], sptr(sAh + r * 72 + c));
            ldsm4(al[mt][0], al[mt][1], al[mt][2], al[mt][3], sptr(sAl + r * 72 + c));
        }
        #pragma unroll
        for (int np = 0; np < 4; np++) {
            int kk = ks + (lane & 7) + ((lane >> 3) & 1) * 8;
            int cc = warp_n * 64 + np * 16 + (lane >> 4) * 8;
            uint32_t bh[4], bl[4];
            ldsm4t(bh[0], bh[1], bh[2], bh[3], sptr(sBh + kk * 136 + cc));
            ldsm4t(bl[0], bl[1], bl[2], bl[3], sptr(sBl + kk * 136 + cc));
            #pragma unroll
            for (int mt = 0; mt < 2; mt++) {
                #pragma unroll
                for (int sub = 0; sub < 2; sub++) {
                    float* c0 = acc[mt][np * 2 + sub];
                    mma16816(c0, ah[mt], bh[sub * 2], bh[sub * 2 + 1]);
                    mma16816(c0, ah[mt], bl[sub * 2], bl[sub * 2 + 1]);
                    mma16816(c0, al[mt], bh[sub * 2], bh[sub * 2 + 1]);
                }
            }
        }
    }

    #pragma unroll
    for (int mt = 0; mt < 2; mt++) {
        int rA = warp_m * 32 + mt * 16 + (lane >> 2);
        int rB = rA + 8;
        float ssA = 0.f, ssB = 0.f;
        #pragma unroll
        for (int nt = 0; nt < 8; nt++) {
            int col = warp_n * 64 + nt * 8 + (lane & 3) * 2;
            float b0 = bias[col], b1 = bias[col + 1];
            float v0 = acc[mt][nt][0] + b0;
            float v1 = acc[mt][nt][1] + b1;
            float v2 = acc[mt][nt][2] + b0;
            float v3 = acc[mt][nt][3] + b1;
            *(float2*)(C + (size_t)(row0 + rA) * 128 + col) = make_float2(v0, v1);
            *(float2*)(C + (size_t)(row0 + rB) * 128 + col) = make_float2(v2, v3);
            ssA += v0 * v0 + v1 * v1;
            ssB += v2 * v2 + v3 * v3;
        }
        ssA = quadsum(ssA); ssB = quadsum(ssB);
        if ((lane & 3) == 0) {
            sred[warp_n * 128 + rA] = ssA;
            sred[warp_n * 128 + rB] = ssB;
        }
    }
    __syncthreads();
    if (tid < 128) ssq_out[row0 + tid] = sred[tid] + sred[128 + tid];
}

// ---------------- fused data-graph layer: reg-staged-CSR AGNN prologue + 2-stage MLP + partial pool ----------------
__global__ __launch_bounds__(256, 2) void mlp_fused(
    const float* __restrict__ h, const float* __restrict__ inv,
    const int* __restrict__ csr_src, const int* __restrict__ start,
    const int* __restrict__ cnt,
    const float* __restrict__ betas, int l, const float* __restrict__ ssqa,
    const bf16* __restrict__ W1h, const bf16* __restrict__ W1l,
    const bf16* __restrict__ W2h, const bf16* __restrict__ W2l,
    const float* __restrict__ bias1, const float* __restrict__ bias2,
    const float* __restrict__ vg,
    float* __restrict__ Cout, float* __restrict__ ssq_out, float* __restrict__ gpart)
{
    extern __shared__ __align__(16) char sm[];
    bf16* sAh = (bf16*)sm;                    // 128*136
    bf16* sAl = sAh + 128 * 136;
    bf16* sBh = sAl + 128 * 136;              // [2][32*136]
    bf16* sBl = sBh + 2 * 32 * 136;
    float* sred = (float*)(sBl + 2 * 32 * 136);   // 256 ssq + 512 colsum

    int tid = threadIdx.x;
    int wid = tid >> 5, lane = tid & 31;
    int warp_m = wid >> 1, warp_n = wid & 1;
    int row0 = blockIdx.x * 128;

    sred[tid] = 0.0f;

    auto load_w = [&](const bf16* Wh_, const bf16* Wl_, int kt, int buf) {
        #pragma unroll
        for (int it = 0; it < 2; it++) {
            int idx = tid + it * 256;
            int r = idx >> 4, f = (idx & 15) * 8;
            cpa16(sBh + buf * 4352 + r * 136 + f, Wh_ + (size_t)(kt * 32 + r) * 128 + f);
            cpa16(sBl + buf * 4352 + r * 136 + f, Wl_ + (size_t)(kt * 32 + r) * 128 + f);
        }
    };

    // prefetch W1 chunks 0,1 so the loads overlap the long gather prologue
    load_w(W1h, W1l, 0, 0); cpcommit();
    load_w(W1h, W1l, 1, 1); cpcommit();

    // ---- per-warp register stage: start/cnt for 16 nodes + up to 192 csr indices ----
    const int n0 = row0 + wid * 16;
    int sc = (lane < 16) ? start[n0 + lane] : cnt[n0 + lane - 16];
    const int wbase = __shfl_sync(0xffffffffu, sc, 0);
    const int wend  = __shfl_sync(0xffffffffu, sc, 15) + __shfl_sync(0xffffffffu, sc, 31);
    const int wcnt  = wend - wbase;
    int idxreg[6];
    #pragma unroll
    for (int t = 0; t < 6; t++) {
        int p = lane + t * 32;
        idxreg[t] = (p < wcnt) ? csr_src[wbase + p] : 0;
    }
    auto getidx = [&](int gp) -> int {
        int p = gp - wbase;
        if (p < 192) {
            int r = p >> 5;
            int v = idxreg[0];
            v = (r == 1) ? idxreg[1] : v;
            v = (r == 2) ? idxreg[2] : v;
            v = (r == 3) ? idxreg[3] : v;
            v = (r == 4) ? idxreg[4] : v;
            v = (r == 5) ? idxreg[5] : v;
            return __shfl_sync(0xffffffffu, v, p & 31);
        }
        return csr_src[gp];
    };

    // ---- AGNN prologue: 8 node-pairs per warp, dual-node chunk-4 gather ----
    float beta = betas[l];
    for (int i = 0; i < 8; i++) {
        int rA = wid * 16 + 2 * i;
        int nA = row0 + rA, nB = nA + 1;
        int cA = __shfl_sync(0xffffffffu, sc, 16 + 2 * i);
        int cB = __shfl_sync(0xffffffffu, sc, 17 + 2 * i);
        float4 accA = make_float4(0.f, 0.f, 0.f, 0.f);
        float4 accB = make_float4(0.f, 0.f, 0.f, 0.f);
        if (cA > 0 || cB > 0) {
            float ex = ssqa[nA >> 9];
            float4 hdA = *(const float4*)(h + (size_t)nA * HD + lane * 4);
            float4 hdB = *(const float4*)(h + (size_t)nB * HD + lane * 4);
            float bsA = beta * inv[nA];
            float bsB = beta * inv[nB];
            int sA0 = __shfl_sync(0xffffffffu, sc, 2 * i);
            int sB0 = __shfl_sync(0xffffffffu, sc, 2 * i + 1);
            float mA = -CUDART_INF_F, denA = 0.f;
            float mB = -CUDART_INF_F, denB = 0.f;
            int jA = 0, jB = 0;
            while (jA < cA || jB < cB) {
                int vA = cA - jA, vB = cB - jB;
                float4 rwA[4], rwB[4]; float eA[4], eB[4];
                #pragma unroll
                for (int j = 0; j < 4; j++) {
                    if (j < vA) {
                        int s = getidx(sA0 + jA + j);
                        rwA[j] = *(const float4*)(h + (size_t)s * HD + lane * 4);
                        eA[j] = inv[s];
                    } else { rwA[j] = make_float4(0.f, 0.f, 0.f, 0.f); eA[j] = 0.f; }
                    if (j < vB) {
                        int s = getidx(sB0 + jB + j);
                        rwB[j] = *(const float4*)(h + (size_t)s * HD + lane * 4);
                        eB[j] = inv[s];
                    } else { rwB[j] = make_float4(0.f, 0.f, 0.f, 0.f); eB[j] = 0.f; }
                }
                float dA[4], dB[4];
                #pragma unroll
                for (int j = 0; j < 4; j++) {
                    dA[j] = rwA[j].x * hdA.x + rwA[j].y * hdA.y + rwA[j].z * hdA.z + rwA[j].w * hdA.w;
                    dB[j] = rwB[j].x * hdB.x + rwB[j].y * hdB.y + rwB[j].z * hdB.z + rwB[j].w * hdB.w;
                }
                #pragma unroll
                for (int o = 16; o; o >>= 1) {
                    #pragma unroll
                    for (int j = 0; j < 4; j++) {
                        dA[j] += __shfl_xor_sync(0xffffffffu, dA[j], o);
                        dB[j] += __shfl_xor_sync(0xffffffffu, dB[j], o);
                    }
                }
                if (vA > 0) {
                    float cm = -CUDART_INF_F;
                    #pragma unroll
                    for (int j = 0; j < 4; j++) {
                        eA[j] = (j < vA) ? (dA[j] + ex) * eA[j] * bsA : -CUDART_INF_F;
                        cm = fmaxf(cm, eA[j]);
                    }
                    float nm = fmaxf(mA, cm);
                    float corr = __expf(mA - nm);
                    denA *= corr; accA.x *= corr; accA.y *= corr; accA.z *= corr; accA.w *= corr;
                    #pragma unroll
                    for (int j = 0; j < 4; j++) {
                        float pp = __expf(eA[j] - nm);
                        denA += pp;
                        accA.x += pp * rwA[j].x; accA.y += pp * rwA[j].y;
                        accA.z += pp * rwA[j].z; accA.w += pp * rwA[j].w;
                    }
                    mA = nm;
                }
                if (vB > 0) {
                    float cm = -CUDART_INF_F;
                    #pragma unroll
                    for (int j = 0; j < 4; j++) {
                        eB[j] = (j < vB) ? (dB[j] + ex) * eB[j] * bsB : -CUDART_INF_F;
                        cm = fmaxf(cm, eB[j]);
                    }
                    float nm = fmaxf(mB, cm);
                    float corr = __expf(mB - nm);
                    denB *= corr; accB.x *= corr; accB.y *= corr; accB.z *= corr; accB.w *= corr;
                    #pragma unroll
                    for (int j = 0; j < 4; j++) {
                        float pp = __expf(eB[j] - nm);
                        denB += pp;
                        accB.x += pp * rwB[j].x; accB.y += pp * rwB[j].y;
                        accB.z += pp * rwB[j].z; accB.w += pp * rwB[j].w;
                    }
                    mB = nm;
                }
                jA += 4; jB += 4;
            }
            if (cA > 0) {
                float rr = 1.0f / fmaxf(denA, 1e-24f);
                accA.x *= rr; accA.y *= rr; accA.z *= rr; accA.w *= rr;
            }
            if (cB > 0) {
                float rr = 1.0f / fmaxf(denB, 1e-24f);
                accB.x *= rr; accB.y *= rr; accB.z *= rr; accB.w *= rr;
            }
        }
        split_store(&sAh[rA * 136 + lane * 4],     &sAl[rA * 136 + lane * 4],     accA.x, accA.y);
        split_store(&sAh[rA * 136 + lane * 4 + 2], &sAl[rA * 136 + lane * 4 + 2], accA.z, accA.w);
        int rB2 = rA + 1;
        split_store(&sAh[rB2 * 136 + lane * 4],     &sAl[rB2 * 136 + lane * 4],     accB.x, accB.y);
        split_store(&sAh[rB2 * 136 + lane * 4 + 2], &sAl[rB2 * 136 + lane * 4 + 2], accB.z, accB.w);
    }

    float acc4[2][8][4];
    #pragma unroll
    for (int i = 0; i < 2; i++)
        #pragma unroll
        for (int j = 0; j < 8; j++)
            #pragma unroll
            for (int k = 0; k < 4; k++) acc4[i][j][k] = 0.0f;

    auto gemm_chunk = [&](int kt, int buf) {
        #pragma unroll
        for (int ksl = 0; ksl < 32; ksl += 16) {
            int ks = kt * 32 + ksl;
            uint32_t ah[2][4], al[2][4];
            #pragma unroll
            for (int mt = 0; mt < 2; mt++) {
                int r = warp_m * 32 + mt * 16 + (lane & 15);
                int c = ks + (lane >> 4) * 8;
                ldsm4(ah[mt][0], ah[mt][1], ah[mt][2], ah[mt][3], sptr(sAh + r * 136 + c));
                ldsm4(al[mt][0], al[mt][1], al[mt][2], al[mt][3], sptr(sAl + r * 136 + c));
            }
            #pragma unroll
            for (int np = 0; np < 4; np++) {
                int kk = ksl + (lane & 7) + ((lane >> 3) & 1) * 8;
                int cc = warp_n * 64 + np * 16 + (lane >> 4) * 8;
                uint32_t bh[4], bl[4];
                ldsm4t(bh[0], bh[1], bh[2], bh[3], sptr(sBh + buf * 4352 + kk * 136 + cc));
                ldsm4t(bl[0], bl[1], bl[2], bl[3], sptr(sBl + buf * 4352 + kk * 136 + cc));
                #pragma unroll
                for (int mt = 0; mt < 2; mt++) {
                    #pragma unroll
                    for (int sub = 0; sub < 2; sub++) {
                        float* c0 = acc4[mt][np * 2 + sub];
                        mma16816(c0, ah[mt], bh[sub * 2], bh[sub * 2 + 1]);
                        mma16816(c0, ah[mt], bl[sub * 2], bl[sub * 2 + 1]);
                        mma16816(c0, al[mt], bh[sub * 2], bh[sub * 2 + 1]);
                    }
                }
            }
        }
    };

    // -------- stage 1 --------
    #pragma unroll
    for (int kt = 0; kt < 4; kt++) {
        if (kt == 3) cpwait<0>(); else cpwait<1>();
        __syncthreads();
        gemm_chunk(kt, kt & 1);
        __syncthreads();
        if (kt + 2 < 4) { load_w(W1h, W1l, kt + 2, kt & 1); cpcommit(); }
    }

    load_w(W2h, W2l, 0, 0); cpcommit();
    load_w(W2h, W2l, 1, 1); cpcommit();

    // stage-1 epilogue: bias1 + vg mask + relu -> restage into sA (split)
    #pragma unroll
    for (int mt = 0; mt < 2; mt++) {
        int rA = warp_m * 32 + mt * 16 + (lane >> 2);
        int rB = rA + 8;
        int gA = row0 + rA, gB = row0 + rB;
        float mA = (cnt[gA] > 0) ? 1.0f : 0.0f;
        float mB = (cnt[gB] > 0) ? 1.0f : 0.0f;
        const float* vA = vg + (size_t)(gA >> 9) * HD;
        const float* vB = vg + (size_t)(gB >> 9) * HD;
        #pragma unroll
        for (int nt = 0; nt < 8; nt++) {
            int col = warp_n * 64 + nt * 8 + (lane & 3) * 2;
            float b0 = bias1[col], b1 = bias1[col + 1];
            float v0 = fmaxf(acc4[mt][nt][0] + b0 + mA * vA[col],     0.f);
            float v1 = fmaxf(acc4[mt][nt][1] + b1 + mA * vA[col + 1], 0.f);
            float v2 = fmaxf(acc4[mt][nt][2] + b0 + mB * vB[col],     0.f);
            float v3 = fmaxf(acc4[mt][nt][3] + b1 + mB * vB[col + 1], 0.f);
            split_store(&sAh[rA * 136 + col], &sAl[rA * 136 + col], v0, v1);
            split_store(&sAh[rB * 136 + col], &sAl[rB * 136 + col], v2, v3);
            acc4[mt][nt][0] = 0.f; acc4[mt][nt][1] = 0.f;
            acc4[mt][nt][2] = 0.f; acc4[mt][nt][3] = 0.f;
        }
    }

    // -------- stage 2 --------
    #pragma unroll
    for (int kt = 0; kt < 4; kt++) {
        if (kt == 3) cpwait<0>(); else cpwait<1>();
        __syncthreads();
        gemm_chunk(kt, kt & 1);
        __syncthreads();
        if (kt + 2 < 4) { load_w(W2h, W2l, kt + 2, kt & 1); cpcommit(); }
    }

    // stage-2 epilogue: bias2, optional store + ssq, column partial sums
    float ps0[8], ps1[8];
    #pragma unroll
    for (int nt = 0; nt < 8; nt++) { ps0[nt] = 0.f; ps1[nt] = 0.f; }
    #pragma unroll
    for (int mt = 0; mt < 2; mt++) {
        int rA = warp_m * 32 + mt * 16 + (lane >> 2);
        int rB = rA + 8;
        float ssA = 0.f, ssB = 0.f;
        #pragma unroll
        for (int nt = 0; nt < 8; nt++) {
            int col = warp_n * 64 + nt * 8 + (lane & 3) * 2;
            float b0 = bias2[col], b1 = bias2[col + 1];
            float v0 = acc4[mt][nt][0] + b0;
            float v1 = acc4[mt][nt][1] + b1;
            float v2 = acc4[mt][nt][2] + b0;
            float v3 = acc4[mt][nt][3] + b1;
            ps0[nt] += v0 + v2;
            ps1[nt] += v1 + v3;
            if (Cout) {
                *(float2*)(Cout + (size_t)(row0 + rA) * 128 + col) = make_float2(v0, v1);
                *(float2*)(Cout + (size_t)(row0 + rB) * 128 + col) = make_float2(v2, v3);
                ssA += v0 * v0 + v1 * v1;
                ssB += v2 * v2 + v3 * v3;
            }
        }
        if (Cout) {
            ssA = quadsum(ssA); ssB = quadsum(ssB);
            if ((lane & 3) == 0) {
                sred[warp_n * 128 + rA] = ssA;
                sred[warp_n * 128 + rB] = ssB;
            }
        }
    }
    #pragma unroll
    for (int nt = 0; nt < 8; nt++) {
        #pragma unroll
        for (int o = 4; o < 32; o <<= 1) {
            ps0[nt] += __shfl_xor_sync(0xffffffffu, ps0[nt], o);
            ps1[nt] += __shfl_xor_sync(0xffffffffu, ps1[nt], o);
        }
    }
    float* scol = sred + 256;     // [4][128]
    if (lane < 4) {
        #pragma unroll
        for (int nt = 0; nt < 8; nt++) {
            int col = warp_n * 64 + nt * 8 + lane * 2;
            scol[warp_m * 128 + col]     = ps0[nt];
            scol[warp_m * 128 + col + 1] = ps1[nt];
        }
    }
    __syncthreads();
    if (tid < 128) {
        gpart[(size_t)blockIdx.x * 128 + tid] =
            scol[tid] + scol[128 + tid] + scol[256 + tid] + scol[384 + tid];
        if (Cout) ssq_out[row0 + tid] = sred[tid] + sred[128 + tid];
    }
}

// ---------------- fused query layer (256 thr, 8 warps x 1 node-pair) ----------------
__global__ __launch_bounds__(256) void qlayer(
    const float* __restrict__ hq, const float* __restrict__ ssq_in,
    const int* __restrict__ csr_src, const int* __restrict__ start,
    const int* __restrict__ cnt,
    const float* __restrict__ betas, int l,
    const float* __restrict__ W1bot,
    float* __restrict__ hq_out, float* __restrict__ ssq_out,
    float* __restrict__ ssqa, float* __restrict__ vgout,
    const float* __restrict__ ssqg, float* __restrict__ invg)
{
    __shared__ float rows[NQPG][132];
    __shared__ float aggs[NQPG][132];
    __shared__ float sssq[NQPG];
    __shared__ float spart[2][HD];
    __shared__ float srow[HD];
    __shared__ float st[HD];
    int g = blockIdx.x, tid = threadIdx.x;
    int wid = tid >> 5, lane = tid & 31;
    int nodebase = g * NQPG;

    // stage input rows (2 per warp) + ssq
    {
        int j = wid * 2;
        *(float4*)&rows[j][lane * 4] =
            *(const float4*)(hq + (size_t)(nodebase + j) * HD + lane * 4);
        *(float4*)&rows[j + 1][lane * 4] =
            *(const float4*)(hq + (size_t)(nodebase + j + 1) * HD + lane * 4);
    }
    if (tid < NQPG) sssq[tid] = ssq_in[nodebase + tid];
    __syncthreads();

    float beta = betas[l];
    {
        int rA = wid * 2, rB = rA + 1;
        int cA = cnt[nodebase + rA], cB = cnt[nodebase + rB];
        float4 accA = make_float4(0.f, 0.f, 0.f, 0.f);
        float4 accB = make_float4(0.f, 0.f, 0.f, 0.f);
        if (cA > 0 || cB > 0) {
            float4 hdA = *(const float4*)&rows[rA][lane * 4];
            float4 hdB = *(const float4*)&rows[rB][lane * 4];
            float invdA = rsqrtf(sssq[rA] + 1e-24f);
            float invdB = rsqrtf(sssq[rB] + 1e-24f);
            int sA0 = start[nodebase + rA], sB0 = start[nodebase + rB];
            float mA = -CUDART_INF_F, denA = 0.f;
            float mB = -CUDART_INF_F, denB = 0.f;
            int jA = 0, jB = 0;
            while (jA < cA || jB < cB) {
                int vA = cA - jA, vB = cB - jB;
                float4 rwA[4], rwB[4]; float eA[4], eB[4];
                #pragma unroll
                for (int j = 0; j < 4; j++) {
                    if (j < vA) {
                        int s = csr_src[sA0 + jA + j] - nodebase;
                        rwA[j] = *(const float4*)&rows[s][lane * 4];
                        eA[j] = sssq[s];
                    } else { rwA[j] = make_float4(0.f, 0.f, 0.f, 0.f); eA[j] = 1.f; }
                    if (j < vB) {
                        int s = csr_src[sB0 + jB + j] - nodebase;
                        rwB[j] = *(const float4*)&rows[s][lane * 4];
                        eB[j] = sssq[s];
                    } else { rwB[j] = make_float4(0.f, 0.f, 0.f, 0.f); eB[j] = 1.f; }
                }
                float dA[4], dB[4];
                #pragma unroll
                for (int j = 0; j < 4; j++) {
                    dA[j] = rwA[j].x * hdA.x + rwA[j].y * hdA.y + rwA[j].z * hdA.z + rwA[j].w * hdA.w;
                    dB[j] = rwB[j].x * hdB.x + rwB[j].y * hdB.y + rwB[j].z * hdB.z + rwB[j].w * hdB.w;
                }
                #pragma unroll
                for (int o = 16; o; o >>= 1) {
                    #pragma unroll
                    for (int j = 0; j < 4; j++) {
                        dA[j] += __shfl_xor_sync(0xffffffffu, dA[j], o);
                        dB[j] += __shfl_xor_sync(0xffffffffu, dB[j], o);
                    }
                }
                if (vA > 0) {
                    float cm = -CUDART_INF_F;
                    #pragma unroll
                    for (int j = 0; j < 4; j++) {
                        eA[j] = (j < vA) ? beta * dA[j] * rsqrtf(eA[j] + 1e-24f) * invdA
                                         : -CUDART_INF_F;
                        cm = fmaxf(cm, eA[j]);
                    }
                    float nm = fmaxf(mA, cm);
                    float corr = __expf(mA - nm);
                    denA *= corr; accA.x *= corr; accA.y *= corr; accA.z *= corr; accA.w *= corr;
                    #pragma unroll
                    for (int j = 0; j < 4; j++) {
                        float pp = __expf(eA[j] - nm);
                        denA += pp;
                        accA.x += pp * rwA[j].x; accA.y += pp * rwA[j].y;
                        accA.z += pp * rwA[j].z; accA.w += pp * rwA[j].w;
                    }
                    mA = nm;
                }
                if (vB > 0) {
                    float cm = -CUDART_INF_F;
                    #pragma unroll
                    for (int j = 0; j < 4; j++) {
                        eB[j] = (j < vB) ? beta * dB[j] * rsqrtf(eB[j] + 1e-24f) * invdB
                                         : -CUDART_INF_F;
                        cm = fmaxf(cm, eB[j]);
                    }
                    float nm = fmaxf(mB, cm);
                    float corr = __expf(mB - nm);
                    denB *= corr; accB.x *= corr; accB.y *= corr; accB.z *= corr; accB.w *= corr;
                    #pragma unroll
                    for (int j = 0; j < 4; j++) {
                        float pp = __expf(eB[j] - nm);
                        denB += pp;
                        accB.x += pp * rwB[j].x; accB.y += pp * rwB[j].y;
                        accB.z += pp * rwB[j].z; accB.w += pp * rwB[j].w;
                    }
                    mB = nm;
                }
                jA += 4; jB += 4;
            }
            if (cA > 0) {
                float rr = 1.0f / fmaxf(denA, 1e-24f);
                accA.x *= rr; accA.y *= rr; accA.z *= rr; accA.w *= rr;
            }
            if (cB > 0) {
                float rr = 1.0f / fmaxf(denB, 1e-24f);
                accB.x *= rr; accB.y *= rr; accB.z *= rr; accB.w *= rr;
            }
        }
        *(float4*)&aggs[rA][lane * 4] = accA;
        *(float4*)&aggs[rB][lane * 4] = accB;
        *(float4*)(hq_out + (size_t)(nodebase + rA) * HD + lane * 4) = accA;
        *(float4*)(hq_out + (size_t)(nodebase + rB) * HD + lane * 4) = accB;
        float sA = accA.x * accA.x + accA.y * accA.y + accA.z * accA.z + accA.w * accA.w;
        float sB = accB.x * accB.x + accB.y * accB.y + accB.z * accB.z + accB.w * accB.w;
        #pragma unroll
        for (int o = 16; o; o >>= 1) {
            sA += __shfl_xor_sync(0xffffffffu, sA, o);
            sB += __shfl_xor_sync(0xffffffffu, sB, o);
        }
        if (lane == 0) {
            ssq_out[nodebase + rA] = sA;
            ssq_out[nodebase + rB] = sB;
        }
    }
    __syncthreads();

    // pool (2-way split) + ssqa
    int col = tid & 127, part = tid >> 7;
    {
        float a = 0.0f;
        #pragma unroll
        for (int j = 0; j < 8; j++) a += aggs[part * 8 + j][col];
        spart[part][col] = a;
    }
    __syncthreads();
    if (tid < 128) {
        float s = spart[0][tid] + spart[1][tid];
        srow[tid] = s;
        st[tid] = s * s;
    }
    __syncthreads();
    #pragma unroll
    for (int o = 64; o; o >>= 1) {
        if (tid < o) st[tid] += st[tid + o];
        __syncthreads();
    }
    float exv = st[0];
    if (tid == 0) ssqa[g] = exv;

    // vg = aggr @ W1bot (2-way k split)
    {
        float v = 0.0f;
        #pragma unroll 8
        for (int k = 0; k < 64; k++)
            v += srow[part * 64 + k] * W1bot[(part * 64 + k) * HD + col];
        spart[part][col] = v;
    }
    __syncthreads();
    if (tid < 128) vgout[g * HD + tid] = spart[0][tid] + spart[1][tid];

    // precompute inv for this block's DATA graph nodes
    #pragma unroll
    for (int j = 0; j < NPG / 256; j++) {
        int n = g * NPG + j * 256 + tid;
        invg[n] = rsqrtf(ssqg[n] + exv + 1e-24f);
    }
}

// ---------------- final predictor from block partials ----------------
__global__ void pool_pred2(const float* __restrict__ gpart, const float* __restrict__ Wp1,
                           const float* __restrict__ bp1, const float* __restrict__ Wp2,
                           const float* __restrict__ bp2, float* __restrict__ y)
{
    __shared__ float srow[HD];
    __shared__ float st[HD];
    int g = blockIdx.x, t = threadIdx.x;   // 128 threads; 4 blocks per graph
    srow[t] = gpart[(size_t)(4 * g) * 128 + t] + gpart[(size_t)(4 * g + 1) * 128 + t]
            + gpart[(size_t)(4 * g + 2) * 128 + t] + gpart[(size_t)(4 * g + 3) * 128 + t];
    __syncthreads();
    float a = 0.0f;
    #pragma unroll 8
    for (int k = 0; k < HD; k++) a += srow[k] * Wp1[k * HD + t];
    st[t] = fmaxf(a + bp1[t], 0.0f) * Wp2[t];
    __syncthreads();
    #pragma unroll
    for (int o = 64; o; o >>= 1) {
        if (t < o) st[t] += st[t + o];
        __syncthreads();
    }
    if (t == 0) y[g] = st[0] + bp2[0];
}

// ---------------- launch ----------------
extern "C" void kernel_launch(void* const* d_in, const int* in_sizes, int n_in,
                              void* d_out, int out_size)
{
    const float* X     = (const float*)d_in[0];
    const float* Xq    = (const float*)d_in[1];
    const int*   g_src = (const int*)d_in[2];
    const int*   g_dst = (const int*)d_in[3];
    const int*   q_src = (const int*)d_in[5];
    const int*   q_dst = (const int*)d_in[6];
    const float* Wg    = (const float*)d_in[8];
    const float* bg    = (const float*)d_in[9];
    const float* Wq    = (const float*)d_in[10];
    const float* bq    = (const float*)d_in[11];
    const float* betas_g = (const float*)d_in[12];
    const float* betas_q = (const float*)d_in[13];
    const float* W1r   = (const float*)d_in[14];
    const float* b1r   = (const float*)d_in[15];
    const float* W2r   = (const float*)d_in[16];
    const float* b2r   = (const float*)d_in[17];
    const float* Wp1   = (const float*)d_in[18];
    const float* bp1   = (const float*)d_in[19];
    const float* Wp2   = (const float*)d_in[20];
    const float* bp2   = (const float*)d_in[21];
    float* y = (float*)d_out;

    float *hgA, *hgB, *hqA, *hqB, *ssqgA, *ssqgB, *ssqqA, *ssqqB, *invg;
    float *ssqa0, *ssqa1, *vg0, *vg1, *part;
    bf16 *Wh, *Wl;
    int *csrg, *startg, *cntg, *csrq, *startq, *cntq;
    cudaGetSymbolAddress((void**)&hgA, d_hgA);
    cudaGetSymbolAddress((void**)&hgB, d_hgB);
    cudaGetSymbolAddress((void**)&hqA, d_hqA);
    cudaGetSymbolAddress((void**)&hqB, d_hqB);
    cudaGetSymbolAddress((void**)&ssqgA, d_ssqgA);
    cudaGetSymbolAddress((void**)&ssqgB, d_ssqgB);
    cudaGetSymbolAddress((void**)&ssqqA, d_ssqqA);
    cudaGetSymbolAddress((void**)&ssqqB, d_ssqqB);
    cudaGetSymbolAddress((void**)&invg, d_invg);
    cudaGetSymbolAddress((void**)&ssqa0, d_ssqa0);
    cudaGetSymbolAddress((void**)&ssqa1, d_ssqa1);
    cudaGetSymbolAddress((void**)&vg0, d_vg0);
    cudaGetSymbolAddress((void**)&vg1, d_vg1);
    cudaGetSymbolAddress((void**)&part, d_part);
    cudaGetSymbolAddress((void**)&Wh, d_Wh);
    cudaGetSymbolAddress((void**)&Wl, d_Wl);
    cudaGetSymbolAddress((void**)&csrg, d_csrg);
    cudaGetSymbolAddress((void**)&startg, d_startg);
    cudaGetSymbolAddress((void**)&cntg, d_cntg);
    cudaGetSymbolAddress((void**)&csrq, d_csrq);
    cudaGetSymbolAddress((void**)&startq, d_startq);
    cudaGetSymbolAddress((void**)&cntq, d_cntq);

    const int SM_IN  = 2 * (128 * 72 * 2) + 2 * (64 * 136 * 2) + 256 * 4;
    const int SM_MLP = 2 * (128 * 136 * 2) + 2 * (2 * 32 * 136 * 2) + (256 + 512) * 4;
    cudaFuncSetAttribute(gemm_in,   cudaFuncAttributeMaxDynamicSharedMemorySize, SM_IN);
    cudaFuncSetAttribute(mlp_fused, cudaFuncAttributeMaxDynamicSharedMemorySize, SM_MLP);

    // setup: data-graph CSR + (query CSR | weight split)
    build_csr3<NPG, EGE / NB, 16><<<NB, 512>>>(g_src, g_dst, csrg, startg, cntg);
    const int WS_BLOCKS = (WTOT / 4 + 127) / 128;    // 160
    setup_q_ws<<<NB + WS_BLOCKS, 128>>>(q_src, q_dst, csrq, startq, cntq,
                                        Wg, Wq, W1r, W2r, Wh, Wl);

    // merged input projections (data + query)
    gemm_in<<<NGN / 128 + NQN / 128, 256, SM_IN>>>(
        X,  Wh + OFF_WG, Wl + OFF_WG, bg, hgA, ssqgA,
        Xq, Wh + OFF_WQ, Wl + OFF_WQ, bq, hqA, ssqqA,
        NGN / 128);

    // layer 0
    qlayer<<<NB, 256>>>(hqA, ssqqA, csrq, startq, cntq, betas_q, 0,
                        W1r + 0 * 2 * HD * HD + HD * HD, hqB, ssqqB, ssqa0, vg0,
                        ssqgA, invg);
    mlp_fused<<<NGN / 128, 256, SM_MLP>>>(hgA, invg, csrg, startg, cntg,
                                          betas_g, 0, ssqa0,
                                          Wh + OFF_W1(0), Wl + OFF_W1(0),
                                          Wh + OFF_W2(0), Wl + OFF_W2(0),
                                          b1r, b2r, vg0, hgB, ssqgB, part);

    // layer 1
    qlayer<<<NB, 256>>>(hqB, ssqqB, csrq, startq, cntq, betas_q, 1,
                        W1r + (size_t)1 * 2 * HD * HD + HD * HD, hqA, ssqqA, ssqa1, vg1,
                        ssqgB, invg);
    mlp_fused<<<NGN / 128, 256, SM_MLP>>>(hgB, invg, csrg, startg, cntg,
                                          betas_g, 1, ssqa1,
                                          Wh + OFF_W1(1), Wl + OFF_W1(1),
                                          Wh + OFF_W2(1), Wl + OFF_W2(1),
                                          b1r + HD, b2r + HD, vg1,
                                          nullptr, nullptr, part);

    pool_pred2<<<NB, 128>>>(part, Wp1, bp1, Wp2, bp2, y);
}

// round 16
// speedup vs baseline: 1.2250x; 1.2250x over previous
#include <cuda_runtime.h>
#include <cuda_bf16.h>
#include <math_constants.h>
#include <cstdint>

#define NB    256
#define NPG   512
#define NGN   131072
#define EGE   1048576
#define NQPG  16
#define NQN   4096
#define EQE   32768
#define FIN   64
#define HD    128
#define NL    2

typedef __nv_bfloat16 bf16;
typedef __nv_bfloat162 bf162;

#define OFF_WG  0
#define OFF_WQ  8192
#define OFF_W1(l) (16384 + (l) * 32768)
#define OFF_W2(l) (16384 + (l) * 32768 + 16384)
#define WTOT    (16384 + NL * 32768)

// ---------------- device scratch ----------------
__device__ __align__(16) float d_hgA[NGN * HD];
__device__ __align__(16) float d_hgB[NGN * HD];
__device__ __align__(16) float d_hqA[NQN * HD];
__device__ __align__(16) float d_hqB[NQN * HD];
__device__ float d_ssqgA[NGN];
__device__ float d_ssqgB[NGN];
__device__ float d_ssqqA[NQN];
__device__ float d_ssqqB[NQN];
__device__ float d_invg[NGN];
__device__ float d_ssqa0[NB];
__device__ float d_ssqa1[NB];
__device__ float d_vg0[NB * HD];
__device__ float d_vg1[NB * HD];
__device__ float d_part[(NGN / 128) * HD];
__device__ __align__(16) bf16 d_Wh[WTOT];
__device__ __align__(16) bf16 d_Wl[WTOT];
__device__ int d_csrg[EGE];      // stores SRC node index per CSR slot
__device__ int d_startg[NGN];
__device__ int d_cntg[NGN];
__device__ int d_csrq[EQE];
__device__ int d_startq[NQN];
__device__ int d_cntq[NQN];

// ---------------- helpers ----------------
__device__ __forceinline__ uint32_t sptr(const void* p) {
    return (uint32_t)__cvta_generic_to_shared(p);
}
__device__ __forceinline__ void ldsm4(uint32_t& r0, uint32_t& r1, uint32_t& r2, uint32_t& r3, uint32_t a) {
    asm volatile("ldmatrix.sync.aligned.m8n8.x4.shared.b16 {%0,%1,%2,%3},[%4];\n"
                 : "=r"(r0), "=r"(r1), "=r"(r2), "=r"(r3) : "r"(a));
}
__device__ __forceinline__ void ldsm4t(uint32_t& r0, uint32_t& r1, uint32_t& r2, uint32_t& r3, uint32_t a) {
    asm volatile("ldmatrix.sync.aligned.m8n8.x4.trans.shared.b16 {%0,%1,%2,%3},[%4];\n"
                 : "=r"(r0), "=r"(r1), "=r"(r2), "=r"(r3) : "r"(a));
}
__device__ __forceinline__ void mma16816(float* c, const uint32_t* a, uint32_t b0, uint32_t b1) {
    asm volatile("mma.sync.aligned.m16n8k16.row.col.f32.bf16.bf16.f32 "
                 "{%0,%1,%2,%3},{%4,%5,%6,%7},{%8,%9},{%0,%1,%2,%3};\n"
                 : "+f"(c[0]), "+f"(c[1]), "+f"(c[2]), "+f"(c[3])
                 : "r"(a[0]), "r"(a[1]), "r"(a[2]), "r"(a[3]), "r"(b0), "r"(b1));
}
__device__ __forceinline__ void cpa16(void* s, const void* g) {
    asm volatile("cp.async.cg.shared.global [%0], [%1], 16;\n" :: "r"(sptr(s)), "l"(g));
}
__device__ __forceinline__ void cpcommit() { asm volatile("cp.async.commit_group;\n"); }
template<int N> __device__ __forceinline__ void cpwait() {
    asm volatile("cp.async.wait_group %0;\n" :: "n"(N));
}
__device__ __forceinline__ void split_store(bf16* hi, bf16* lo, float x, float y) {
    bf162 h = __floats2bfloat162_rn(x, y);
    bf162 l = __floats2bfloat162_rn(x - __bfloat162float(h.x), y - __bfloat162float(h.y));
    *(bf162*)hi = h;
    *(bf162*)lo = l;
}
__device__ __forceinline__ float quadsum(float v) {
    v += __shfl_xor_sync(0xffffffffu, v, 1);
    v += __shfl_xor_sync(0xffffffffu, v, 2);
    return v;
}

// ---------------- O(E) deterministic CSR build (stores src idx, parallel scan) ----------------
template<int NPGT, int EPGT, int W>
__global__ void build_csr3(const int* __restrict__ src, const int* __restrict__ dst,
                           int* __restrict__ csr_src,
                           int* __restrict__ start,
                           int* __restrict__ cnt)
{
    __shared__ int hw[W][NPGT];
    __shared__ int wsum[32];
    const int g = blockIdx.x;
    const int nodebase = g * NPGT, edgebase = g * EPGT;
    const int tid = threadIdx.x, w = tid >> 5, lane = tid & 31;
    const int EPW = EPGT / W;

    for (int i = tid; i < W * NPGT; i += W * 32) ((int*)hw)[i] = 0;
    __syncthreads();

    const int ebase = edgebase + w * EPW;
    for (int c0 = 0; c0 < EPW; c0 += 32) {
        int d = dst[ebase + c0 + lane] - nodebase;
        unsigned mm = __match_any_sync(0xffffffffu, d);
        int leader = __ffs(mm) - 1;
        if (lane == leader) atomicAdd(&hw[w][d], __popc(mm));
    }
    __syncthreads();

    int deg = 0, excl = 0;
    if (tid < NPGT) {
        #pragma unroll
        for (int ww = 0; ww < W; ww++) deg += hw[ww][tid];
        cnt[nodebase + tid] = deg;
    }
    if constexpr (NPGT >= 64) {
        int inc = deg;
        #pragma unroll
        for (int o = 1; o < 32; o <<= 1) {
            int n = __shfl_up_sync(0xffffffffu, inc, o);
            if (lane >= o) inc += n;
        }
        if (lane == 31) wsum[w] = inc;
        __syncthreads();
        if (tid < 32) {
            int s = (tid < NPGT / 32) ? wsum[tid] : 0;
            #pragma unroll
            for (int o = 1; o < 32; o <<= 1) {
                int n = __shfl_up_sync(0xffffffffu, s, o);
                if (tid >= o) s += n;
            }
            if (tid < NPGT / 32) wsum[tid] = s;
        }
        __syncthreads();
        excl = inc - deg + (w ? wsum[w - 1] : 0);
    } else {
        __shared__ int soff[NPGT];
        if (tid < NPGT) soff[tid] = deg;
        __syncthreads();
        if (tid == 0) {
            int run = 0;
            for (int i = 0; i < NPGT; i++) { int d0 = soff[i]; soff[i] = run; run += d0; }
        }
        __syncthreads();
        if (tid < NPGT) excl = soff[tid];
    }
    __syncthreads();
    if (tid < NPGT) {
        int run = edgebase + excl;
        start[nodebase + tid] = run;
        #pragma unroll
        for (int ww = 0; ww < W; ww++) { int t0 = hw[ww][tid]; hw[ww][tid] = run; run += t0; }
    }
    __syncthreads();

    for (int c0 = 0; c0 < EPW; c0 += 32) {
        int e = ebase + c0 + lane;
        int d = dst[e] - nodebase;
        int sv = src[e];
        unsigned mm = __match_any_sync(0xffffffffu, d);
        int leader = __ffs(mm) - 1;
        int r = __popc(mm & ((1u << lane) - 1));
        int basepos = 0;
        if (lane == leader) { basepos = hw[w][d]; hw[w][d] += __popc(mm); }
        basepos = __shfl_sync(0xffffffffu, basepos, leader);
        csr_src[basepos + r] = sv;
    }
}

// ---------------- merged: query CSR build + weight split (block-range branch) ----------------
__global__ void setup_q_ws(const int* __restrict__ qsrc, const int* __restrict__ qdst,
                           int* __restrict__ csrq, int* __restrict__ startq, int* __restrict__ cntq,
                           const float* __restrict__ Wg, const float* __restrict__ Wq,
                           const float* __restrict__ W1r, const float* __restrict__ W2r,
                           bf16* __restrict__ Wh, bf16* __restrict__ Wl)
{
    if ((int)blockIdx.x < NB) {
        constexpr int NPGT = NQPG, EPGT = EQE / NB, W = 4;
        __shared__ int hw[W][NPGT];
        __shared__ int soff[NPGT];
        const int g = blockIdx.x;
        const int nodebase = g * NPGT, edgebase = g * EPGT;
        const int tid = threadIdx.x, w = tid >> 5, lane = tid & 31;
        const int EPW = EPGT / W;

        for (int i = tid; i < W * NPGT; i += 128) ((int*)hw)[i] = 0;
        __syncthreads();

        const int ebase = edgebase + w * EPW;
        for (int c0 = 0; c0 < EPW; c0 += 32) {
            int d = qdst[ebase + c0 + lane] - nodebase;
            unsigned mm = __match_any_sync(0xffffffffu, d);
            int leader = __ffs(mm) - 1;
            if (lane == leader) atomicAdd(&hw[w][d], __popc(mm));
        }
        __syncthreads();

        int deg = 0;
        if (tid < NPGT) {
            #pragma unroll
            for (int ww = 0; ww < W; ww++) deg += hw[ww][tid];
            cntq[nodebase + tid] = deg;
            soff[tid] = deg;
        }
        __syncthreads();
        if (tid == 0) {
            int run = 0;
            for (int i = 0; i < NPGT; i++) { int d0 = soff[i]; soff[i] = run; run += d0; }
        }
        __syncthreads();
        if (tid < NPGT) {
            int run = edgebase + soff[tid];
            startq[nodebase + tid] = run;
            #pragma unroll
            for (int ww = 0; ww < W; ww++) { int t0 = hw[ww][tid]; hw[ww][tid] = run; run += t0; }
        }
        __syncthreads();

        for (int c0 = 0; c0 < EPW; c0 += 32) {
            int e = ebase + c0 + lane;
            int d = qdst[e] - nodebase;
            int sv = qsrc[e];
            unsigned mm = __match_any_sync(0xffffffffu, d);
            int leader = __ffs(mm) - 1;
            int r = __popc(mm & ((1u << lane) - 1));
            int basepos = 0;
            if (lane == leader) { basepos = hw[w][d]; hw[w][d] += __popc(mm); }
            basepos = __shfl_sync(0xffffffffu, basepos, leader);
            csrq[basepos + r] = sv;
        }
    } else {
        int i4 = ((int)blockIdx.x - NB) * 128 + threadIdx.x;
        int e0 = i4 * 4;
        if (e0 >= WTOT) return;
        const float* src;
        if (e0 < 8192) src = Wg + e0;
        else if (e0 < 16384) src = Wq + (e0 - 8192);
        else {
            int t = e0 - 16384;
            int l = t / 32768, r = t % 32768;
            if (r < 16384) src = W1r + (size_t)l * 32768 + r;
            else           src = W2r + (size_t)l * 16384 + (r - 16384);
        }
        float4 v = *(const float4*)src;
        split_store(Wh + e0,     Wl + e0,     v.x, v.y);
        split_store(Wh + e0 + 2, Wl + e0 + 2, v.z, v.w);
    }
}

// ---------------- merged input projection GEMM (K=64, two operand sets) ----------------
__global__ __launch_bounds__(256, 2) void gemm_in(
    const float* __restrict__ A0, const bf16* __restrict__ Bh0, const bf16* __restrict__ Bl0,
    const float* __restrict__ bias0, float* __restrict__ C0, float* __restrict__ ssq0,
    const float* __restrict__ A1, const bf16* __restrict__ Bh1, const bf16* __restrict__ Bl1,
    const float* __restrict__ bias1, float* __restrict__ C1, float* __restrict__ ssq1,
    int nb0)
{
    extern __shared__ __align__(16) char sm[];
    bf16* sAh = (bf16*)sm;
    bf16* sAl = sAh + 128 * 72;
    bf16* sBh = sAl + 128 * 72;
    bf16* sBl = sBh + 64 * 136;
    float* sred = (float*)(sBl + 64 * 136);

    int tid = threadIdx.x;
    int wid = tid >> 5, lane = tid & 31;
    int warp_m = wid >> 1, warp_n = wid & 1;

    const float* A; const bf16* Bh; const bf16* Bl; const float* bias;
    float* C; float* ssq_out; int row0;
    if ((int)blockIdx.x < nb0) {
        A = A0; Bh = Bh0; Bl = Bl0; bias = bias0; C = C0; ssq_out = ssq0;
        row0 = blockIdx.x * 128;
    } else {
        A = A1; Bh = Bh1; Bl = Bl1; bias = bias1; C = C1; ssq_out = ssq1;
        row0 = (blockIdx.x - nb0) * 128;
    }

    sred[tid] = 0.0f;

    #pragma unroll
    for (int it = 0; it < 8; it++) {
        int idx = tid + it * 256;
        int m = idx >> 4, f = (idx & 15) * 4;
        float4 v = *(const float4*)(A + (size_t)(row0 + m) * FIN + f);
        split_store(&sAh[m * 72 + f],     &sAl[m * 72 + f],     v.x, v.y);
        split_store(&sAh[m * 72 + f + 2], &sAl[m * 72 + f + 2], v.z, v.w);
    }
    #pragma unroll
    for (int it = 0; it < 4; it++) {
        int idx = tid + it * 256;
        int kk = idx >> 4, f = (idx & 15) * 8;
        *(float4*)(sBh + kk * 136 + f) = *(const float4*)(Bh + kk * 128 + f);
        *(float4*)(sBl + kk * 136 + f) = *(const float4*)(Bl + kk * 128 + f);
    }
    __syncthreads();

    float acc[2][8][4];
    #pragma unroll
    for (int i = 0; i < 2; i++)
        #pragma unroll
        for (int j = 0; j < 8; j++)
            #pragma unroll
            for (int k = 0; k < 4; k++) acc[i][j][k] = 0.0f;

    #pragma unroll
    for (int ks = 0; ks < FIN; ks += 16) {
        uint32_t ah[2][4], al[2][4];
        #pragma unroll
        for (int mt = 0; mt < 2; mt++) {
            int r = warp_m * 32 + mt * 16 + (lane & 15);
            int c = ks + (lane >> 4) * 8;
            ldsm4(ah[mt][0], ah[mt][1], ah[mt][2], ah[mt][3], sptr(sAh + r * 72 + c));
            ldsm4(al[mt][0], al[mt][1], al[mt][2], al[mt][3], sptr(sAl + r * 72 + c));
        }
        #pragma unroll
        for (int np = 0; np < 4; np++) {
            int kk = ks + (lane & 7) + ((lane >> 3) & 1) * 8;
            int cc = warp_n * 64 + np * 16 + (lane >> 4) * 8;
            uint32_t bh[4], bl[4];
            ldsm4t(bh[0], bh[1], bh[2], bh[3], sptr(sBh + kk * 136 + cc));
            ldsm4t(bl[0], bl[1], bl[2], bl[3], sptr(sBl + kk * 136 + cc));
            #pragma unroll
            for (int mt = 0; mt < 2; mt++) {
                #pragma unroll
                for (int sub = 0; sub < 2; sub++) {
                    float* c0 = acc[mt][np * 2 + sub];
                    mma16816(c0, ah[mt], bh[sub * 2], bh[sub * 2 + 1]);
                    mma16816(c0, ah[mt], bl[sub * 2], bl[sub * 2 + 1]);
                    mma16816(c0, al[mt], bh[sub * 2], bh[sub * 2 + 1]);
                }
            }
        }
    }

    #pragma unroll
    for (int mt = 0; mt < 2; mt++) {
        int rA = warp_m * 32 + mt * 16 + (lane >> 2);
        int rB = rA + 8;
        float ssA = 0.f, ssB = 0.f;
        #pragma unroll
        for (int nt = 0; nt < 8; nt++) {
            int col = warp_n * 64 + nt * 8 + (lane & 3) * 2;
            float b0 = bias[col], b1 = bias[col + 1];
            float v0 = acc[mt][nt][0] + b0;
            float v1 = acc[mt][nt][1] + b1;
            float v2 = acc[mt][nt][2] + b0;
            float v3 = acc[mt][nt][3] + b1;
            *(float2*)(C + (size_t)(row0 + rA) * 128 + col) = make_float2(v0, v1);
            *(float2*)(C + (size_t)(row0 + rB) * 128 + col) = make_float2(v2, v3);
            ssA += v0 * v0 + v1 * v1;
            ssB += v2 * v2 + v3 * v3;
        }
        ssA = quadsum(ssA); ssB = quadsum(ssB);
        if ((lane & 3) == 0) {
            sred[warp_n * 128 + rA] = ssA;
            sred[warp_n * 128 + rB] = ssB;
        }
    }
    __syncthreads();
    if (tid < 128) ssq_out[row0 + tid] = sred[tid] + sred[128 + tid];
}

// ---------------- fused data-graph layer: dual-node AGNN prologue + 2-stage MLP + partial pool ----------------
// gather uses precomputed per-node inv = rsqrt(ssq + ssqa_g + eps)
__global__ __launch_bounds__(256, 2) void mlp_fused(
    const float* __restrict__ h, const float* __restrict__ inv,
    const int* __restrict__ csr_src, const int* __restrict__ start,
    const int* __restrict__ cnt,
    const float* __restrict__ betas, int l, const float* __restrict__ ssqa,
    const bf16* __restrict__ W1h, const bf16* __restrict__ W1l,
    const bf16* __restrict__ W2h, const bf16* __restrict__ W2l,
    const float* __restrict__ bias1, const float* __restrict__ bias2,
    const float* __restrict__ vg,
    float* __restrict__ Cout, float* __restrict__ ssq_out, float* __restrict__ gpart)
{
    extern __shared__ __align__(16) char sm[];
    bf16* sAh = (bf16*)sm;                    // 128*136
    bf16* sAl = sAh + 128 * 136;
    bf16* sBh = sAl + 128 * 136;              // [2][32*136]
    bf16* sBl = sBh + 2 * 32 * 136;
    float* sred = (float*)(sBl + 2 * 32 * 136);   // 256 ssq + 512 colsum

    int tid = threadIdx.x;
    int wid = tid >> 5, lane = tid & 31;
    int warp_m = wid >> 1, warp_n = wid & 1;
    int row0 = blockIdx.x * 128;

    sred[tid] = 0.0f;

    auto load_w = [&](const bf16* Wh_, const bf16* Wl_, int kt, int buf) {
        #pragma unroll
        for (int it = 0; it < 2; it++) {
            int idx = tid + it * 256;
            int r = idx >> 4, f = (idx & 15) * 8;
            cpa16(sBh + buf * 4352 + r * 136 + f, Wh_ + (size_t)(kt * 32 + r) * 128 + f);
            cpa16(sBl + buf * 4352 + r * 136 + f, Wl_ + (size_t)(kt * 32 + r) * 128 + f);
        }
    };

    // prefetch W1 chunks 0,1 so the loads overlap the long gather prologue
    load_w(W1h, W1l, 0, 0); cpcommit();
    load_w(W1h, W1l, 1, 1); cpcommit();

    // ---- AGNN prologue: 8 node-pairs per warp, dual-node chunk-4 gather ----
    float beta = betas[l];
    for (int i = 0; i < 8; i++) {
        int rA = wid * 16 + 2 * i;
        int nA = row0 + rA, nB = nA + 1;
        int cA = cnt[nA], cB = cnt[nB];
        float4 accA = make_float4(0.f, 0.f, 0.f, 0.f);
        float4 accB = make_float4(0.f, 0.f, 0.f, 0.f);
        if (cA > 0 || cB > 0) {
            float ex = ssqa[nA >> 9];
            float4 hdA = *(const float4*)(h + (size_t)nA * HD + lane * 4);
            float4 hdB = *(const float4*)(h + (size_t)nB * HD + lane * 4);
            float bsA = beta * inv[nA];
            float bsB = beta * inv[nB];
            int sA0 = start[nA], sB0 = start[nB];
            float mA = -CUDART_INF_F, denA = 0.f;
            float mB = -CUDART_INF_F, denB = 0.f;
            int jA = 0, jB = 0;
            while (jA < cA || jB < cB) {
                int vA = cA - jA, vB = cB - jB;
                float4 rwA[4], rwB[4]; float eA[4], eB[4];
                #pragma unroll
                for (int j = 0; j < 4; j++) {
                    if (j < vA) {
                        int s = csr_src[sA0 + jA + j];
                        rwA[j] = *(const float4*)(h + (size_t)s * HD + lane * 4);
                        eA[j] = inv[s];
                    } else { rwA[j] = make_float4(0.f, 0.f, 0.f, 0.f); eA[j] = 0.f; }
                    if (j < vB) {
                        int s = csr_src[sB0 + jB + j];
                        rwB[j] = *(const float4*)(h + (size_t)s * HD + lane * 4);
                        eB[j] = inv[s];
                    } else { rwB[j] = make_float4(0.f, 0.f, 0.f, 0.f); eB[j] = 0.f; }
                }
                float dA[4], dB[4];
                #pragma unroll
                for (int j = 0; j < 4; j++) {
                    dA[j] = rwA[j].x * hdA.x + rwA[j].y * hdA.y + rwA[j].z * hdA.z + rwA[j].w * hdA.w;
                    dB[j] = rwB[j].x * hdB.x + rwB[j].y * hdB.y + rwB[j].z * hdB.z + rwB[j].w * hdB.w;
                }
                #pragma unroll
                for (int o = 16; o; o >>= 1) {
                    #pragma unroll
                    for (int j = 0; j < 4; j++) {
                        dA[j] += __shfl_xor_sync(0xffffffffu, dA[j], o);
                        dB[j] += __shfl_xor_sync(0xffffffffu, dB[j], o);
                    }
                }
                if (vA > 0) {
                    float cm = -CUDART_INF_F;
                    #pragma unroll
                    for (int j = 0; j < 4; j++) {
                        eA[j] = (j < vA) ? (dA[j] + ex) * eA[j] * bsA : -CUDART_INF_F;
                        cm = fmaxf(cm, eA[j]);
                    }
                    float nm = fmaxf(mA, cm);
                    float corr = __expf(mA - nm);
                    denA *= corr; accA.x *= corr; accA.y *= corr; accA.z *= corr; accA.w *= corr;
                    #pragma unroll
                    for (int j = 0; j < 4; j++) {
                        float pp = __expf(eA[j] - nm);
                        denA += pp;
                        accA.x += pp * rwA[j].x; accA.y += pp * rwA[j].y;
                        accA.z += pp * rwA[j].z; accA.w += pp * rwA[j].w;
                    }
                    mA = nm;
                }
                if (vB > 0) {
                    float cm = -CUDART_INF_F;
                    #pragma unroll
                    for (int j = 0; j < 4; j++) {
                        eB[j] = (j < vB) ? (dB[j] + ex) * eB[j] * bsB : -CUDART_INF_F;
                        cm = fmaxf(cm, eB[j]);
                    }
                    float nm = fmaxf(mB, cm);
                    float corr = __expf(mB - nm);
                    denB *= corr; accB.x *= corr; accB.y *= corr; accB.z *= corr; accB.w *= corr;
                    #pragma unroll
                    for (int j = 0; j < 4; j++) {
                        float pp = __expf(eB[j] - nm);
                        denB += pp;
                        accB.x += pp * rwB[j].x; accB.y += pp * rwB[j].y;
                        accB.z += pp * rwB[j].z; accB.w += pp * rwB[j].w;
                    }
                    mB = nm;
                }
                jA += 4; jB += 4;
            }
            if (cA > 0) {
                float rr = 1.0f / fmaxf(denA, 1e-24f);
                accA.x *= rr; accA.y *= rr; accA.z *= rr; accA.w *= rr;
            }
            if (cB > 0) {
                float rr = 1.0f / fmaxf(denB, 1e-24f);
                accB.x *= rr; accB.y *= rr; accB.z *= rr; accB.w *= rr;
            }
        }
        split_store(&sAh[rA * 136 + lane * 4],     &sAl[rA * 136 + lane * 4],     accA.x, accA.y);
        split_store(&sAh[rA * 136 + lane * 4 + 2], &sAl[rA * 136 + lane * 4 + 2], accA.z, accA.w);
        int rB2 = rA + 1;
        split_store(&sAh[rB2 * 136 + lane * 4],     &sAl[rB2 * 136 + lane * 4],     accB.x, accB.y);
        split_store(&sAh[rB2 * 136 + lane * 4 + 2], &sAl[rB2 * 136 + lane * 4 + 2], accB.z, accB.w);
    }

    float acc4[2][8][4];
    #pragma unroll
    for (int i = 0; i < 2; i++)
        #pragma unroll
        for (int j = 0; j < 8; j++)
            #pragma unroll
            for (int k = 0; k < 4; k++) acc4[i][j][k] = 0.0f;

    auto gemm_chunk = [&](int kt, int buf) {
        #pragma unroll
        for (int ksl = 0; ksl < 32; ksl += 16) {
            int ks = kt * 32 + ksl;
            uint32_t ah[2][4], al[2][4];
            #pragma unroll
            for (int mt = 0; mt < 2; mt++) {
                int r = warp_m * 32 + mt * 16 + (lane & 15);
                int c = ks + (lane >> 4) * 8;
                ldsm4(ah[mt][0], ah[mt][1], ah[mt][2], ah[mt][3], sptr(sAh + r * 136 + c));
                ldsm4(al[mt][0], al[mt][1], al[mt][2], al[mt][3], sptr(sAl + r * 136 + c));
            }
            #pragma unroll
            for (int np = 0; np < 4; np++) {
                int kk = ksl + (lane & 7) + ((lane >> 3) & 1) * 8;
                int cc = warp_n * 64 + np * 16 + (lane >> 4) * 8;
                uint32_t bh[4], bl[4];
                ldsm4t(bh[0], bh[1], bh[2], bh[3], sptr(sBh + buf * 4352 + kk * 136 + cc));
                ldsm4t(bl[0], bl[1], bl[2], bl[3], sptr(sBl + buf * 4352 + kk * 136 + cc));
                #pragma unroll
                for (int mt = 0; mt < 2; mt++) {
                    #pragma unroll
                    for (int sub = 0; sub < 2; sub++) {
                        float* c0 = acc4[mt][np * 2 + sub];
                        mma16816(c0, ah[mt], bh[sub * 2], bh[sub * 2 + 1]);
                        mma16816(c0, ah[mt], bl[sub * 2], bl[sub * 2 + 1]);
                        mma16816(c0, al[mt], bh[sub * 2], bh[sub * 2 + 1]);
                    }
                }
            }
        }
    };

    // -------- stage 1 --------
    #pragma unroll
    for (int kt = 0; kt < 4; kt++) {
        if (kt == 3) cpwait<0>(); else cpwait<1>();
        __syncthreads();
        gemm_chunk(kt, kt & 1);
        __syncthreads();
        if (kt + 2 < 4) { load_w(W1h, W1l, kt + 2, kt & 1); cpcommit(); }
    }

    load_w(W2h, W2l, 0, 0); cpcommit();
    load_w(W2h, W2l, 1, 1); cpcommit();

    // stage-1 epilogue: bias1 + vg mask + relu -> restage into sA (split)
    #pragma unroll
    for (int mt = 0; mt < 2; mt++) {
        int rA = warp_m * 32 + mt * 16 + (lane >> 2);
        int rB = rA + 8;
        int gA = row0 + rA, gB = row0 + rB;
        float mA = (cnt[gA] > 0) ? 1.0f : 0.0f;
        float mB = (cnt[gB] > 0) ? 1.0f : 0.0f;
        const float* vA = vg + (size_t)(gA >> 9) * HD;
        const float* vB = vg + (size_t)(gB >> 9) * HD;
        #pragma unroll
        for (int nt = 0; nt < 8; nt++) {
            int col = warp_n * 64 + nt * 8 + (lane & 3) * 2;
            float b0 = bias1[col], b1 = bias1[col + 1];
            float v0 = fmaxf(acc4[mt][nt][0] + b0 + mA * vA[col],     0.f);
            float v1 = fmaxf(acc4[mt][nt][1] + b1 + mA * vA[col + 1], 0.f);
            float v2 = fmaxf(acc4[mt][nt][2] + b0 + mB * vB[col],     0.f);
            float v3 = fmaxf(acc4[mt][nt][3] + b1 + mB * vB[col + 1], 0.f);
            split_store(&sAh[rA * 136 + col], &sAl[rA * 136 + col], v0, v1);
            split_store(&sAh[rB * 136 + col], &sAl[rB * 136 + col], v2, v3);
            acc4[mt][nt][0] = 0.f; acc4[mt][nt][1] = 0.f;
            acc4[mt][nt][2] = 0.f; acc4[mt][nt][3] = 0.f;
        }
    }

    // -------- stage 2 --------
    #pragma unroll
    for (int kt = 0; kt < 4; kt++) {
        if (kt == 3) cpwait<0>(); else cpwait<1>();
        __syncthreads();
        gemm_chunk(kt, kt & 1);
        __syncthreads();
        if (kt + 2 < 4) { load_w(W2h, W2l, kt + 2, kt & 1); cpcommit(); }
    }

    // stage-2 epilogue: bias2, optional store + ssq, column partial sums
    float ps0[8], ps1[8];
    #pragma unroll
    for (int nt = 0; nt < 8; nt++) { ps0[nt] = 0.f; ps1[nt] = 0.f; }
    #pragma unroll
    for (int mt = 0; mt < 2; mt++) {
        int rA = warp_m * 32 + mt * 16 + (lane >> 2);
        int rB = rA + 8;
        float ssA = 0.f, ssB = 0.f;
        #pragma unroll
        for (int nt = 0; nt < 8; nt++) {
            int col = warp_n * 64 + nt * 8 + (lane & 3) * 2;
            float b0 = bias2[col], b1 = bias2[col + 1];
            float v0 = acc4[mt][nt][0] + b0;
            float v1 = acc4[mt][nt][1] + b1;
            float v2 = acc4[mt][nt][2] + b0;
            float v3 = acc4[mt][nt][3] + b1;
            ps0[nt] += v0 + v2;
            ps1[nt] += v1 + v3;
            if (Cout) {
                *(float2*)(Cout + (size_t)(row0 + rA) * 128 + col) = make_float2(v0, v1);
                *(float2*)(Cout + (size_t)(row0 + rB) * 128 + col) = make_float2(v2, v3);
                ssA += v0 * v0 + v1 * v1;
                ssB += v2 * v2 + v3 * v3;
            }
        }
        if (Cout) {
            ssA = quadsum(ssA); ssB = quadsum(ssB);
            if ((lane & 3) == 0) {
                sred[warp_n * 128 + rA] = ssA;
                sred[warp_n * 128 + rB] = ssB;
            }
        }
    }
    #pragma unroll
    for (int nt = 0; nt < 8; nt++) {
        #pragma unroll
        for (int o = 4; o < 32; o <<= 1) {
            ps0[nt] += __shfl_xor_sync(0xffffffffu, ps0[nt], o);
            ps1[nt] += __shfl_xor_sync(0xffffffffu, ps1[nt], o);
        }
    }
    float* scol = sred + 256;     // [4][128]
    if (lane < 4) {
        #pragma unroll
        for (int nt = 0; nt < 8; nt++) {
            int col = warp_n * 64 + nt * 8 + lane * 2;
            scol[warp_m * 128 + col]     = ps0[nt];
            scol[warp_m * 128 + col + 1] = ps1[nt];
        }
    }
    __syncthreads();
    if (tid < 128) {
        gpart[(size_t)blockIdx.x * 128 + tid] =
            scol[tid] + scol[128 + tid] + scol[256 + tid] + scol[384 + tid];
        if (Cout) ssq_out[row0 + tid] = sred[tid] + sred[128 + tid];
    }
}

// ---------------- fused query layer (256 thr, 8 warps x 1 node-pair) ----------------
__global__ __launch_bounds__(256) void qlayer(
    const float* __restrict__ hq, const float* __restrict__ ssq_in,
    const int* __restrict__ csr_src, const int* __restrict__ start,
    const int* __restrict__ cnt,
    const float* __restrict__ betas, int l,
    const float* __restrict__ W1bot,
    float* __restrict__ hq_out, float* __restrict__ ssq_out,
    float* __restrict__ ssqa, float* __restrict__ vgout,
    const float* __restrict__ ssqg, float* __restrict__ invg)
{
    __shared__ float rows[NQPG][132];
    __shared__ float aggs[NQPG][132];
    __shared__ float sssq[NQPG];
    __shared__ float spart[2][HD];
    __shared__ float srow[HD];
    __shared__ float st[HD];
    int g = blockIdx.x, tid = threadIdx.x;
    int wid = tid >> 5, lane = tid & 31;
    int nodebase = g * NQPG;

    // stage input rows (2 per warp) + ssq
    {
        int j = wid * 2;
        *(float4*)&rows[j][lane * 4] =
            *(const float4*)(hq + (size_t)(nodebase + j) * HD + lane * 4);
        *(float4*)&rows[j + 1][lane * 4] =
            *(const float4*)(hq + (size_t)(nodebase + j + 1) * HD + lane * 4);
    }
    if (tid < NQPG) sssq[tid] = ssq_in[nodebase + tid];
    __syncthreads();

    float beta = betas[l];
    {
        int rA = wid * 2, rB = rA + 1;
        int cA = cnt[nodebase + rA], cB = cnt[nodebase + rB];
        float4 accA = make_float4(0.f, 0.f, 0.f, 0.f);
        float4 accB = make_float4(0.f, 0.f, 0.f, 0.f);
        if (cA > 0 || cB > 0) {
            float4 hdA = *(const float4*)&rows[rA][lane * 4];
            float4 hdB = *(const float4*)&rows[rB][lane * 4];
            float invdA = rsqrtf(sssq[rA] + 1e-24f);
            float invdB = rsqrtf(sssq[rB] + 1e-24f);
            int sA0 = start[nodebase + rA], sB0 = start[nodebase + rB];
            float mA = -CUDART_INF_F, denA = 0.f;
            float mB = -CUDART_INF_F, denB = 0.f;
            int jA = 0, jB = 0;
            while (jA < cA || jB < cB) {
                int vA = cA - jA, vB = cB - jB;
                float4 rwA[4], rwB[4]; float eA[4], eB[4];
                #pragma unroll
                for (int j = 0; j < 4; j++) {
                    if (j < vA) {
                        int s = csr_src[sA0 + jA + j] - nodebase;
                        rwA[j] = *(const float4*)&rows[s][lane * 4];
                        eA[j] = sssq[s];
                    } else { rwA[j] = make_float4(0.f, 0.f, 0.f, 0.f); eA[j] = 1.f; }
                    if (j < vB) {
                        int s = csr_src[sB0 + jB + j] - nodebase;
                        rwB[j] = *(const float4*)&rows[s][lane * 4];
                        eB[j] = sssq[s];
                    } else { rwB[j] = make_float4(0.f, 0.f, 0.f, 0.f); eB[j] = 1.f; }
                }
                float dA[4], dB[4];
                #pragma unroll
                for (int j = 0; j < 4; j++) {
                    dA[j] = rwA[j].x * hdA.x + rwA[j].y * hdA.y + rwA[j].z * hdA.z + rwA[j].w * hdA.w;
                    dB[j] = rwB[j].x * hdB.x + rwB[j].y * hdB.y + rwB[j].z * hdB.z + rwB[j].w * hdB.w;
                }
                #pragma unroll
                for (int o = 16; o; o >>= 1) {
                    #pragma unroll
                    for (int j = 0; j < 4; j++) {
                        dA[j] += __shfl_xor_sync(0xffffffffu, dA[j], o);
                        dB[j] += __shfl_xor_sync(0xffffffffu, dB[j], o);
                    }
                }
                if (vA > 0) {
                    float cm = -CUDART_INF_F;
                    #pragma unroll
                    for (int j = 0; j < 4; j++) {
                        eA[j] = (j < vA) ? beta * dA[j] * rsqrtf(eA[j] + 1e-24f) * invdA
                                         : -CUDART_INF_F;
                        cm = fmaxf(cm, eA[j]);
                    }
                    float nm = fmaxf(mA, cm);
                    float corr = __expf(mA - nm);
                    denA *= corr; accA.x *= corr; accA.y *= corr; accA.z *= corr; accA.w *= corr;
                    #pragma unroll
                    for (int j = 0; j < 4; j++) {
                        float pp = __expf(eA[j] - nm);
                        denA += pp;
                        accA.x += pp * rwA[j].x; accA.y += pp * rwA[j].y;
                        accA.z += pp * rwA[j].z; accA.w += pp * rwA[j].w;
                    }
                    mA = nm;
                }
                if (vB > 0) {
                    float cm = -CUDART_INF_F;
                    #pragma unroll
                    for (int j = 0; j < 4; j++) {
                        eB[j] = (j < vB) ? beta * dB[j] * rsqrtf(eB[j] + 1e-24f) * invdB
                                         : -CUDART_INF_F;
                        cm = fmaxf(cm, eB[j]);
                    }
                    float nm = fmaxf(mB, cm);
                    float corr = __expf(mB - nm);
                    denB *= corr; accB.x *= corr; accB.y *= corr; accB.z *= corr; accB.w *= corr;
                    #pragma unroll
                    for (int j = 0; j < 4; j++) {
                        float pp = __expf(eB[j] - nm);
                        denB += pp;
                        accB.x += pp * rwB[j].x; accB.y += pp * rwB[j].y;
                        accB.z += pp * rwB[j].z; accB.w += pp * rwB[j].w;
                    }
                    mB = nm;
                }
                jA += 4; jB += 4;
            }
            if (cA > 0) {
                float rr = 1.0f / fmaxf(denA, 1e-24f);
                accA.x *= rr; accA.y *= rr; accA.z *= rr; accA.w *= rr;
            }
            if (cB > 0) {
                float rr = 1.0f / fmaxf(denB, 1e-24f);
                accB.x *= rr; accB.y *= rr; accB.z *= rr; accB.w *= rr;
            }
        }
        *(float4*)&aggs[rA][lane * 4] = accA;
        *(float4*)&aggs[rB][lane * 4] = accB;
        *(float4*)(hq_out + (size_t)(nodebase + rA) * HD + lane * 4) = accA;
        *(float4*)(hq_out + (size_t)(nodebase + rB) * HD + lane * 4) = accB;
        float sA = accA.x * accA.x + accA.y * accA.y + accA.z * accA.z + accA.w * accA.w;
        float sB = accB.x * accB.x + accB.y * accB.y + accB.z * accB.z + accB.w * accB.w;
        #pragma unroll
        for (int o = 16; o; o >>= 1) {
            sA += __shfl_xor_sync(0xffffffffu, sA, o);
            sB += __shfl_xor_sync(0xffffffffu, sB, o);
        }
        if (lane == 0) {
            ssq_out[nodebase + rA] = sA;
            ssq_out[nodebase + rB] = sB;
        }
    }
    __syncthreads();

    // pool (2-way split) + ssqa
    int col = tid & 127, part = tid >> 7;
    {
        float a = 0.0f;
        #pragma unroll
        for (int j = 0; j < 8; j++) a += aggs[part * 8 + j][col];
        spart[part][col] = a;
    }
    __syncthreads();
    if (tid < 128) {
        float s = spart[0][tid] + spart[1][tid];
        srow[tid] = s;
        st[tid] = s * s;
    }
    __syncthreads();
    #pragma unroll
    for (int o = 64; o; o >>= 1) {
        if (tid < o) st[tid] += st[tid + o];
        __syncthreads();
    }
    float exv = st[0];
    if (tid == 0) ssqa[g] = exv;

    // vg = aggr @ W1bot (2-way k split)
    {
        float v = 0.0f;
        #pragma unroll 8
        for (int k = 0; k < 64; k++)
            v += srow[part * 64 + k] * W1bot[(part * 64 + k) * HD + col];
        spart[part][col] = v;
    }
    __syncthreads();
    if (tid < 128) vgout[g * HD + tid] = spart[0][tid] + spart[1][tid];

    // precompute inv for this block's DATA graph nodes
    #pragma unroll
    for (int j = 0; j < NPG / 256; j++) {
        int n = g * NPG + j * 256 + tid;
        invg[n] = rsqrtf(ssqg[n] + exv + 1e-24f);
    }
}

// ---------------- final predictor from block partials ----------------
__global__ void pool_pred2(const float* __restrict__ gpart, const float* __restrict__ Wp1,
                           const float* __restrict__ bp1, const float* __restrict__ Wp2,
                           const float* __restrict__ bp2, float* __restrict__ y)
{
    __shared__ float srow[HD];
    __shared__ float st[HD];
    int g = blockIdx.x, t = threadIdx.x;   // 128 threads; 4 blocks per graph
    srow[t] = gpart[(size_t)(4 * g) * 128 + t] + gpart[(size_t)(4 * g + 1) * 128 + t]
            + gpart[(size_t)(4 * g + 2) * 128 + t] + gpart[(size_t)(4 * g + 3) * 128 + t];
    __syncthreads();
    float a = 0.0f;
    #pragma unroll 8
    for (int k = 0; k < HD; k++) a += srow[k] * Wp1[k * HD + t];
    st[t] = fmaxf(a + bp1[t], 0.0f) * Wp2[t];
    __syncthreads();
    #pragma unroll
    for (int o = 64; o; o >>= 1) {
        if (t < o) st[t] += st[t + o];
        __syncthreads();
    }
    if (t == 0) y[g] = st[0] + bp2[0];
}

// ---------------- launch ----------------
extern "C" void kernel_launch(void* const* d_in, const int* in_sizes, int n_in,
                              void* d_out, int out_size)
{
    const float* X     = (const float*)d_in[0];
    const float* Xq    = (const float*)d_in[1];
    const int*   g_src = (const int*)d_in[2];
    const int*   g_dst = (const int*)d_in[3];
    const int*   q_src = (const int*)d_in[5];
    const int*   q_dst = (const int*)d_in[6];
    const float* Wg    = (const float*)d_in[8];
    const float* bg    = (const float*)d_in[9];
    const float* Wq    = (const float*)d_in[10];
    const float* bq    = (const float*)d_in[11];
    const float* betas_g = (const float*)d_in[12];
    const float* betas_q = (const float*)d_in[13];
    const float* W1r   = (const float*)d_in[14];
    const float* b1r   = (const float*)d_in[15];
    const float* W2r   = (const float*)d_in[16];
    const float* b2r   = (const float*)d_in[17];
    const float* Wp1   = (const float*)d_in[18];
    const float* bp1   = (const float*)d_in[19];
    const float* Wp2   = (const float*)d_in[20];
    const float* bp2   = (const float*)d_in[21];
    float* y = (float*)d_out;

    float *hgA, *hgB, *hqA, *hqB, *ssqgA, *ssqgB, *ssqqA, *ssqqB, *invg;
    float *ssqa0, *ssqa1, *vg0, *vg1, *part;
    bf16 *Wh, *Wl;
    int *csrg, *startg, *cntg, *csrq, *startq, *cntq;
    cudaGetSymbolAddress((void**)&hgA, d_hgA);
    cudaGetSymbolAddress((void**)&hgB, d_hgB);
    cudaGetSymbolAddress((void**)&hqA, d_hqA);
    cudaGetSymbolAddress((void**)&hqB, d_hqB);
    cudaGetSymbolAddress((void**)&ssqgA, d_ssqgA);
    cudaGetSymbolAddress((void**)&ssqgB, d_ssqgB);
    cudaGetSymbolAddress((void**)&ssqqA, d_ssqqA);
    cudaGetSymbolAddress((void**)&ssqqB, d_ssqqB);
    cudaGetSymbolAddress((void**)&invg, d_invg);
    cudaGetSymbolAddress((void**)&ssqa0, d_ssqa0);
    cudaGetSymbolAddress((void**)&ssqa1, d_ssqa1);
    cudaGetSymbolAddress((void**)&vg0, d_vg0);
    cudaGetSymbolAddress((void**)&vg1, d_vg1);
    cudaGetSymbolAddress((void**)&part, d_part);
    cudaGetSymbolAddress((void**)&Wh, d_Wh);
    cudaGetSymbolAddress((void**)&Wl, d_Wl);
    cudaGetSymbolAddress((void**)&csrg, d_csrg);
    cudaGetSymbolAddress((void**)&startg, d_startg);
    cudaGetSymbolAddress((void**)&cntg, d_cntg);
    cudaGetSymbolAddress((void**)&csrq, d_csrq);
    cudaGetSymbolAddress((void**)&startq, d_startq);
    cudaGetSymbolAddress((void**)&cntq, d_cntq);

    const int SM_IN  = 2 * (128 * 72 * 2) + 2 * (64 * 136 * 2) + 256 * 4;
    const int SM_MLP = 2 * (128 * 136 * 2) + 2 * (2 * 32 * 136 * 2) + (256 + 512) * 4;
    cudaFuncSetAttribute(gemm_in,   cudaFuncAttributeMaxDynamicSharedMemorySize, SM_IN);
    cudaFuncSetAttribute(mlp_fused, cudaFuncAttributeMaxDynamicSharedMemorySize, SM_MLP);

    // setup: data-graph CSR + (query CSR | weight split)
    build_csr3<NPG, EGE / NB, 16><<<NB, 512>>>(g_src, g_dst, csrg, startg, cntg);
    const int WS_BLOCKS = (WTOT / 4 + 127) / 128;    // 160
    setup_q_ws<<<NB + WS_BLOCKS, 128>>>(q_src, q_dst, csrq, startq, cntq,
                                        Wg, Wq, W1r, W2r, Wh, Wl);

    // merged input projections (data + query)
    gemm_in<<<NGN / 128 + NQN / 128, 256, SM_IN>>>(
        X,  Wh + OFF_WG, Wl + OFF_WG, bg, hgA, ssqgA,
        Xq, Wh + OFF_WQ, Wl + OFF_WQ, bq, hqA, ssqqA,
        NGN / 128);

    // layer 0
    qlayer<<<NB, 256>>>(hqA, ssqqA, csrq, startq, cntq, betas_q, 0,
                        W1r + 0 * 2 * HD * HD + HD * HD, hqB, ssqqB, ssqa0, vg0,
                        ssqgA, invg);
    mlp_fused<<<NGN / 128, 256, SM_MLP>>>(hgA, invg, csrg, startg, cntg,
                                          betas_g, 0, ssqa0,
                                          Wh + OFF_W1(0), Wl + OFF_W1(0),
                                          Wh + OFF_W2(0), Wl + OFF_W2(0),
                                          b1r, b2r, vg0, hgB, ssqgB, part);

    // layer 1
    qlayer<<<NB, 256>>>(hqB, ssqqB, csrq, startq, cntq, betas_q, 1,
                        W1r + (size_t)1 * 2 * HD * HD + HD * HD, hqA, ssqqA, ssqa1, vg1,
                        ssqgB, invg);
    mlp_fused<<<NGN / 128, 256, SM_MLP>>>(hgB, invg, csrg, startg, cntg,
                                          betas_g, 1, ssqa1,
                                          Wh + OFF_W1(1), Wl + OFF_W1(1),
                                          Wh + OFF_W2(1), Wl + OFF_W2(1),
                                          b1r + HD, b2r + HD, vg1,
                                          nullptr, nullptr, part);

    pool_pred2<<<NB, 128>>>(part, Wp1, bp1, Wp2, bp2, y);
}

// round 17
// speedup vs baseline: 1.2468x; 1.0177x over previous
#include <cuda_runtime.h>
#include <cuda_bf16.h>
#include <math_constants.h>
#include <cstdint>

#define NB    256
#define NPG   512
#define NGN   131072
#define EGE   1048576
#define NQPG  16
#define NQN   4096
#define EQE   32768
#define FIN   64
#define HD    128
#define NL    2

typedef __nv_bfloat16 bf16;
typedef __nv_bfloat162 bf162;

#define OFF_WG  0
#define OFF_WQ  8192
#define OFF_W1(l) (16384 + (l) * 32768)
#define OFF_W2(l) (16384 + (l) * 32768 + 16384)
#define WTOT    (16384 + NL * 32768)

// ---------------- device scratch ----------------
__device__ __align__(16) float d_hgA[NGN * HD];
__device__ __align__(16) float d_hgB[NGN * HD];
__device__ __align__(16) float d_hqA[NQN * HD];
__device__ __align__(16) float d_hqB[NQN * HD];
__device__ float d_ssqgA[NGN];
__device__ float d_ssqgB[NGN];
__device__ float d_ssqqA[NQN];
__device__ float d_ssqqB[NQN];
__device__ float d_invg[NGN];
__device__ float d_ssqa0[NB];
__device__ float d_ssqa1[NB];
__device__ float d_vg0[NB * HD];
__device__ float d_vg1[NB * HD];
__device__ float d_part[(NGN / 128) * HD];
__device__ __align__(16) bf16 d_Wh[WTOT];
__device__ __align__(16) bf16 d_Wl[WTOT];
__device__ int d_csrg[EGE];      // stores SRC node index per CSR slot
__device__ int d_startg[NGN];
__device__ int d_cntg[NGN];
__device__ int d_csrq[EQE];
__device__ int d_startq[NQN];
__device__ int d_cntq[NQN];

// ---------------- helpers ----------------
__device__ __forceinline__ uint32_t sptr(const void* p) {
    return (uint32_t)__cvta_generic_to_shared(p);
}
__device__ __forceinline__ void ldsm4(uint32_t& r0, uint32_t& r1, uint32_t& r2, uint32_t& r3, uint32_t a) {
    asm volatile("ldmatrix.sync.aligned.m8n8.x4.shared.b16 {%0,%1,%2,%3},[%4];\n"
                 : "=r"(r0), "=r"(r1), "=r"(r2), "=r"(r3) : "r"(a));
}
__device__ __forceinline__ void ldsm4t(uint32_t& r0, uint32_t& r1, uint32_t& r2, uint32_t& r3, uint32_t a) {
    asm volatile("ldmatrix.sync.aligned.m8n8.x4.trans.shared.b16 {%0,%1,%2,%3},[%4];\n"
                 : "=r"(r0), "=r"(r1), "=r"(r2), "=r"(r3) : "r"(a));
}
__device__ __forceinline__ void mma16816(float* c, const uint32_t* a, uint32_t b0, uint32_t b1) {
    asm volatile("mma.sync.aligned.m16n8k16.row.col.f32.bf16.bf16.f32 "
                 "{%0,%1,%2,%3},{%4,%5,%6,%7},{%8,%9},{%0,%1,%2,%3};\n"
                 : "+f"(c[0]), "+f"(c[1]), "+f"(c[2]), "+f"(c[3])
                 : "r"(a[0]), "r"(a[1]), "r"(a[2]), "r"(a[3]), "r"(b0), "r"(b1));
}
__device__ __forceinline__ void cpa16(void* s, const void* g) {
    asm volatile("cp.async.cg.shared.global [%0], [%1], 16;\n" :: "r"(sptr(s)), "l"(g));
}
__device__ __forceinline__ void cpcommit() { asm volatile("cp.async.commit_group;\n"); }
template<int N> __device__ __forceinline__ void cpwait() {
    asm volatile("cp.async.wait_group %0;\n" :: "n"(N));
}
__device__ __forceinline__ void split_store(bf16* hi, bf16* lo, float x, float y) {
    bf162 h = __floats2bfloat162_rn(x, y);
    bf162 l = __floats2bfloat162_rn(x - __bfloat162float(h.x), y - __bfloat162float(h.y));
    *(bf162*)hi = h;
    *(bf162*)lo = l;
}
__device__ __forceinline__ float quadsum(float v) {
    v += __shfl_xor_sync(0xffffffffu, v, 1);
    v += __shfl_xor_sync(0xffffffffu, v, 2);
    return v;
}

// ---------------- O(E) deterministic CSR build (stores src idx, parallel scan) ----------------
template<int NPGT, int EPGT, int W>
__global__ void build_csr3(const int* __restrict__ src, const int* __restrict__ dst,
                           int* __restrict__ csr_src,
                           int* __restrict__ start,
                           int* __restrict__ cnt)
{
    __shared__ int hw[W][NPGT];
    __shared__ int wsum[32];
    const int g = blockIdx.x;
    const int nodebase = g * NPGT, edgebase = g * EPGT;
    const int tid = threadIdx.x, w = tid >> 5, lane = tid & 31;
    const int EPW = EPGT / W;

    for (int i = tid; i < W * NPGT; i += W * 32) ((int*)hw)[i] = 0;
    __syncthreads();

    const int ebase = edgebase + w * EPW;
    for (int c0 = 0; c0 < EPW; c0 += 32) {
        int d = dst[ebase + c0 + lane] - nodebase;
        unsigned mm = __match_any_sync(0xffffffffu, d);
        int leader = __ffs(mm) - 1;
        if (lane == leader) atomicAdd(&hw[w][d], __popc(mm));
    }
    __syncthreads();

    int deg = 0, excl = 0;
    if (tid < NPGT) {
        #pragma unroll
        for (int ww = 0; ww < W; ww++) deg += hw[ww][tid];
        cnt[nodebase + tid] = deg;
    }
    if constexpr (NPGT >= 64) {
        int inc = deg;
        #pragma unroll
        for (int o = 1; o < 32; o <<= 1) {
            int n = __shfl_up_sync(0xffffffffu, inc, o);
            if (lane >= o) inc += n;
        }
        if (lane == 31) wsum[w] = inc;
        __syncthreads();
        if (tid < 32) {
            int s = (tid < NPGT / 32) ? wsum[tid] : 0;
            #pragma unroll
            for (int o = 1; o < 32; o <<= 1) {
                int n = __shfl_up_sync(0xffffffffu, s, o);
                if (tid >= o) s += n;
            }
            if (tid < NPGT / 32) wsum[tid] = s;
        }
        __syncthreads();
        excl = inc - deg + (w ? wsum[w - 1] : 0);
    } else {
        __shared__ int soff[NPGT];
        if (tid < NPGT) soff[tid] = deg;
        __syncthreads();
        if (tid == 0) {
            int run = 0;
            for (int i = 0; i < NPGT; i++) { int d0 = soff[i]; soff[i] = run; run += d0; }
        }
        __syncthreads();
        if (tid < NPGT) excl = soff[tid];
    }
    __syncthreads();
    if (tid < NPGT) {
        int run = edgebase + excl;
        start[nodebase + tid] = run;
        #pragma unroll
        for (int ww = 0; ww < W; ww++) { int t0 = hw[ww][tid]; hw[ww][tid] = run; run += t0; }
    }
    __syncthreads();

    for (int c0 = 0; c0 < EPW; c0 += 32) {
        int e = ebase + c0 + lane;
        int d = dst[e] - nodebase;
        int sv = src[e];
        unsigned mm = __match_any_sync(0xffffffffu, d);
        int leader = __ffs(mm) - 1;
        int r = __popc(mm & ((1u << lane) - 1));
        int basepos = 0;
        if (lane == leader) { basepos = hw[w][d]; hw[w][d] += __popc(mm); }
        basepos = __shfl_sync(0xffffffffu, basepos, leader);
        csr_src[basepos + r] = sv;
    }
}

// ---------------- merged: query CSR build + weight split (block-range branch) ----------------
__global__ void setup_q_ws(const int* __restrict__ qsrc, const int* __restrict__ qdst,
                           int* __restrict__ csrq, int* __restrict__ startq, int* __restrict__ cntq,
                           const float* __restrict__ Wg, const float* __restrict__ Wq,
                           const float* __restrict__ W1r, const float* __restrict__ W2r,
                           bf16* __restrict__ Wh, bf16* __restrict__ Wl)
{
    if ((int)blockIdx.x < NB) {
        constexpr int NPGT = NQPG, EPGT = EQE / NB, W = 4;
        __shared__ int hw[W][NPGT];
        __shared__ int soff[NPGT];
        const int g = blockIdx.x;
        const int nodebase = g * NPGT, edgebase = g * EPGT;
        const int tid = threadIdx.x, w = tid >> 5, lane = tid & 31;
        const int EPW = EPGT / W;

        for (int i = tid; i < W * NPGT; i += 128) ((int*)hw)[i] = 0;
        __syncthreads();

        const int ebase = edgebase + w * EPW;
        for (int c0 = 0; c0 < EPW; c0 += 32) {
            int d = qdst[ebase + c0 + lane] - nodebase;
            unsigned mm = __match_any_sync(0xffffffffu, d);
            int leader = __ffs(mm) - 1;
            if (lane == leader) atomicAdd(&hw[w][d], __popc(mm));
        }
        __syncthreads();

        int deg = 0;
        if (tid < NPGT) {
            #pragma unroll
            for (int ww = 0; ww < W; ww++) deg += hw[ww][tid];
            cntq[nodebase + tid] = deg;
            soff[tid] = deg;
        }
        __syncthreads();
        if (tid == 0) {
            int run = 0;
            for (int i = 0; i < NPGT; i++) { int d0 = soff[i]; soff[i] = run; run += d0; }
        }
        __syncthreads();
        if (tid < NPGT) {
            int run = edgebase + soff[tid];
            startq[nodebase + tid] = run;
            #pragma unroll
            for (int ww = 0; ww < W; ww++) { int t0 = hw[ww][tid]; hw[ww][tid] = run; run += t0; }
        }
        __syncthreads();

        for (int c0 = 0; c0 < EPW; c0 += 32) {
            int e = ebase + c0 + lane;
            int d = qdst[e] - nodebase;
            int sv = qsrc[e];
            unsigned mm = __match_any_sync(0xffffffffu, d);
            int leader = __ffs(mm) - 1;
            int r = __popc(mm & ((1u << lane) - 1));
            int basepos = 0;
            if (lane == leader) { basepos = hw[w][d]; hw[w][d] += __popc(mm); }
            basepos = __shfl_sync(0xffffffffu, basepos, leader);
            csrq[basepos + r] = sv;
        }
    } else {
        int i4 = ((int)blockIdx.x - NB) * 128 + threadIdx.x;
        int e0 = i4 * 4;
        if (e0 >= WTOT) return;
        const float* src;
        if (e0 < 8192) src = Wg + e0;
        else if (e0 < 16384) src = Wq + (e0 - 8192);
        else {
            int t = e0 - 16384;
            int l = t / 32768, r = t % 32768;
            if (r < 16384) src = W1r + (size_t)l * 32768 + r;
            else           src = W2r + (size_t)l * 16384 + (r - 16384);
        }
        float4 v = *(const float4*)src;
        split_store(Wh + e0,     Wl + e0,     v.x, v.y);
        split_store(Wh + e0 + 2, Wl + e0 + 2, v.z, v.w);
    }
}

// ---------------- merged input projection GEMM (K=64, two operand sets) ----------------
__global__ __launch_bounds__(256, 2) void gemm_in(
    const float* __restrict__ A0, const bf16* __restrict__ Bh0, const bf16* __restrict__ Bl0,
    const float* __restrict__ bias0, float* __restrict__ C0, float* __restrict__ ssq0,
    const float* __restrict__ A1, const bf16* __restrict__ Bh1, const bf16* __restrict__ Bl1,
    const float* __restrict__ bias1, float* __restrict__ C1, float* __restrict__ ssq1,
    int nb0)
{
    extern __shared__ __align__(16) char sm[];
    bf16* sAh = (bf16*)sm;
    bf16* sAl = sAh + 128 * 72;
    bf16* sBh = sAl + 128 * 72;
    bf16* sBl = sBh + 64 * 136;
    float* sred = (float*)(sBl + 64 * 136);

    int tid = threadIdx.x;
    int wid = tid >> 5, lane = tid & 31;
    int warp_m = wid >> 1, warp_n = wid & 1;

    const float* A; const bf16* Bh; const bf16* Bl; const float* bias;
    float* C; float* ssq_out; int row0;
    if ((int)blockIdx.x < nb0) {
        A = A0; Bh = Bh0; Bl = Bl0; bias = bias0; C = C0; ssq_out = ssq0;
        row0 = blockIdx.x * 128;
    } else {
        A = A1; Bh = Bh1; Bl = Bl1; bias = bias1; C = C1; ssq_out = ssq1;
        row0 = (blockIdx.x - nb0) * 128;
    }

    sred[tid] = 0.0f;

    #pragma unroll
    for (int it = 0; it < 8; it++) {
        int idx = tid + it * 256;
        int m = idx >> 4, f = (idx & 15) * 4;
        float4 v = *(const float4*)(A + (size_t)(row0 + m) * FIN + f);
        split_store(&sAh[m * 72 + f],     &sAl[m * 72 + f],     v.x, v.y);
        split_store(&sAh[m * 72 + f + 2], &sAl[m * 72 + f + 2], v.z, v.w);
    }
    #pragma unroll
    for (int it = 0; it < 4; it++) {
        int idx = tid + it * 256;
        int kk = idx >> 4, f = (idx & 15) * 8;
        *(float4*)(sBh + kk * 136 + f) = *(const float4*)(Bh + kk * 128 + f);
        *(float4*)(sBl + kk * 136 + f) = *(const float4*)(Bl + kk * 128 + f);
    }
    __syncthreads();

    float acc[2][8][4];
    #pragma unroll
    for (int i = 0; i < 2; i++)
        #pragma unroll
        for (int j = 0; j < 8; j++)
            #pragma unroll
            for (int k = 0; k < 4; k++) acc[i][j][k] = 0.0f;

    #pragma unroll
    for (int ks = 0; ks < FIN; ks += 16) {
        uint32_t ah[2][4], al[2][4];
        #pragma unroll
        for (int mt = 0; mt < 2; mt++) {
            int r = warp_m * 32 + mt * 16 + (lane & 15);
            int c = ks + (lane >> 4) * 8;
            ldsm4(ah[mt][0], ah[mt][1], ah[mt][2], ah[mt][3], sptr(sAh + r * 72 + c));
            ldsm4(al[mt][0], al[mt][1], al[mt][2], al[mt][3], sptr(sAl + r * 72 + c));
        }
        #pragma unroll
        for (int np = 0; np < 4; np++) {
            int kk = ks + (lane & 7) + ((lane >> 3) & 1) * 8;
            int cc = warp_n * 64 + np * 16 + (lane >> 4) * 8;
            uint32_t bh[4], bl[4];
            ldsm4t(bh[0], bh[1], bh[2], bh[3], sptr(sBh + kk * 136 + cc));
            ldsm4t(bl[0], bl[1], bl[2], bl[3], sptr(sBl + kk * 136 + cc));
            #pragma unroll
            for (int mt = 0; mt < 2; mt++) {
                #pragma unroll
                for (int sub = 0; sub < 2; sub++) {
                    float* c0 = acc[mt][np * 2 + sub];
                    mma16816(c0, ah[mt], bh[sub * 2], bh[sub * 2 + 1]);
                    mma16816(c0, ah[mt], bl[sub * 2], bl[sub * 2 + 1]);
                    mma16816(c0, al[mt], bh[sub * 2], bh[sub * 2 + 1]);
                }
            }
        }
    }

    #pragma unroll
    for (int mt = 0; mt < 2; mt++) {
        int rA = warp_m * 32 + mt * 16 + (lane >> 2);
        int rB = rA + 8;
        float ssA = 0.f, ssB = 0.f;
        #pragma unroll
        for (int nt = 0; nt < 8; nt++) {
            int col = warp_n * 64 + nt * 8 + (lane & 3) * 2;
            float b0 = bias[col], b1 = bias[col + 1];
            float v0 = acc[mt][nt][0] + b0;
            float v1 = acc[mt][nt][1] + b1;
            float v2 = acc[mt][nt][2] + b0;
            float v3 = acc[mt][nt][3] + b1;
            *(float2*)(C + (size_t)(row0 + rA) * 128 + col) = make_float2(v0, v1);
            *(float2*)(C + (size_t)(row0 + rB) * 128 + col) = make_float2(v2, v3);
            ssA += v0 * v0 + v1 * v1;
            ssB += v2 * v2 + v3 * v3;
        }
        ssA = quadsum(ssA); ssB = quadsum(ssB);
        if ((lane & 3) == 0) {
            sred[warp_n * 128 + rA] = ssA;
            sred[warp_n * 128 + rB] = ssB;
        }
    }
    __syncthreads();
    if (tid < 128) ssq_out[row0 + tid] = sred[tid] + sred[128 + tid];
}

// ---------------- fused data-graph layer: dual-node AGNN prologue + 2-stage MLP + partial pool ----------------
// gather uses precomputed per-node inv = rsqrt(ssq + ssqa_g + eps)
// softmax uses FIXED offset C=|beta| (logits are beta*cosine, bounded by |beta|): no online max chain
__global__ __launch_bounds__(256, 2) void mlp_fused(
    const float* __restrict__ h, const float* __restrict__ inv,
    const int* __restrict__ csr_src, const int* __restrict__ start,
    const int* __restrict__ cnt,
    const float* __restrict__ betas, int l, const float* __restrict__ ssqa,
    const bf16* __restrict__ W1h, const bf16* __restrict__ W1l,
    const bf16* __restrict__ W2h, const bf16* __restrict__ W2l,
    const float* __restrict__ bias1, const float* __restrict__ bias2,
    const float* __restrict__ vg,
    float* __restrict__ Cout, float* __restrict__ ssq_out, float* __restrict__ gpart)
{
    extern __shared__ __align__(16) char sm[];
    bf16* sAh = (bf16*)sm;                    // 128*136
    bf16* sAl = sAh + 128 * 136;
    bf16* sBh = sAl + 128 * 136;              // [2][32*136]
    bf16* sBl = sBh + 2 * 32 * 136;
    float* sred = (float*)(sBl + 2 * 32 * 136);   // 256 ssq + 512 colsum

    int tid = threadIdx.x;
    int wid = tid >> 5, lane = tid & 31;
    int warp_m = wid >> 1, warp_n = wid & 1;
    int row0 = blockIdx.x * 128;

    sred[tid] = 0.0f;

    auto load_w = [&](const bf16* Wh_, const bf16* Wl_, int kt, int buf) {
        #pragma unroll
        for (int it = 0; it < 2; it++) {
            int idx = tid + it * 256;
            int r = idx >> 4, f = (idx & 15) * 8;
            cpa16(sBh + buf * 4352 + r * 136 + f, Wh_ + (size_t)(kt * 32 + r) * 128 + f);
            cpa16(sBl + buf * 4352 + r * 136 + f, Wl_ + (size_t)(kt * 32 + r) * 128 + f);
        }
    };

    // prefetch W1 chunks 0,1 so the loads overlap the long gather prologue
    load_w(W1h, W1l, 0, 0); cpcommit();
    load_w(W1h, W1l, 1, 1); cpcommit();

    // ---- AGNN prologue: 8 node-pairs per warp, dual-node chunk-4 gather ----
    float beta = betas[l];
    float Cb = fabsf(beta);
    for (int i = 0; i < 8; i++) {
        int rA = wid * 16 + 2 * i;
        int nA = row0 + rA, nB = nA + 1;
        int cA = cnt[nA], cB = cnt[nB];
        float4 accA = make_float4(0.f, 0.f, 0.f, 0.f);
        float4 accB = make_float4(0.f, 0.f, 0.f, 0.f);
        if (cA > 0 || cB > 0) {
            float ex = ssqa[nA >> 9];
            float4 hdA = *(const float4*)(h + (size_t)nA * HD + lane * 4);
            float4 hdB = *(const float4*)(h + (size_t)nB * HD + lane * 4);
            float bsA = beta * inv[nA];
            float bsB = beta * inv[nB];
            int sA0 = start[nA], sB0 = start[nB];
            float denA = 0.f, denB = 0.f;
            int jA = 0, jB = 0;
            while (jA < cA || jB < cB) {
                int vA = cA - jA, vB = cB - jB;
                float4 rwA[4], rwB[4]; float eA[4], eB[4];
                #pragma unroll
                for (int j = 0; j < 4; j++) {
                    if (j < vA) {
                        int s = csr_src[sA0 + jA + j];
                        rwA[j] = *(const float4*)(h + (size_t)s * HD + lane * 4);
                        eA[j] = inv[s];
                    } else { rwA[j] = make_float4(0.f, 0.f, 0.f, 0.f); eA[j] = 0.f; }
                    if (j < vB) {
                        int s = csr_src[sB0 + jB + j];
                        rwB[j] = *(const float4*)(h + (size_t)s * HD + lane * 4);
                        eB[j] = inv[s];
                    } else { rwB[j] = make_float4(0.f, 0.f, 0.f, 0.f); eB[j] = 0.f; }
                }
                float dA[4], dB[4];
                #pragma unroll
                for (int j = 0; j < 4; j++) {
                    dA[j] = rwA[j].x * hdA.x + rwA[j].y * hdA.y + rwA[j].z * hdA.z + rwA[j].w * hdA.w;
                    dB[j] = rwB[j].x * hdB.x + rwB[j].y * hdB.y + rwB[j].z * hdB.z + rwB[j].w * hdB.w;
                }
                #pragma unroll
                for (int o = 16; o; o >>= 1) {
                    #pragma unroll
                    for (int j = 0; j < 4; j++) {
                        dA[j] += __shfl_xor_sync(0xffffffffu, dA[j], o);
                        dB[j] += __shfl_xor_sync(0xffffffffu, dB[j], o);
                    }
                }
                #pragma unroll
                for (int j = 0; j < 4; j++) {
                    float evA = (j < vA) ? (dA[j] + ex) * eA[j] * bsA - Cb : -CUDART_INF_F;
                    float ppA = __expf(evA);
                    denA += ppA;
                    accA.x += ppA * rwA[j].x; accA.y += ppA * rwA[j].y;
                    accA.z += ppA * rwA[j].z; accA.w += ppA * rwA[j].w;
                    float evB = (j < vB) ? (dB[j] + ex) * eB[j] * bsB - Cb : -CUDART_INF_F;
                    float ppB = __expf(evB);
                    denB += ppB;
                    accB.x += ppB * rwB[j].x; accB.y += ppB * rwB[j].y;
                    accB.z += ppB * rwB[j].z; accB.w += ppB * rwB[j].w;
                }
                jA += 4; jB += 4;
            }
            if (cA > 0) {
                float rr = 1.0f / fmaxf(denA, 1e-24f);
                accA.x *= rr; accA.y *= rr; accA.z *= rr; accA.w *= rr;
            }
            if (cB > 0) {
                float rr = 1.0f / fmaxf(denB, 1e-24f);
                accB.x *= rr; accB.y *= rr; accB.z *= rr; accB.w *= rr;
            }
        }
        split_store(&sAh[rA * 136 + lane * 4],     &sAl[rA * 136 + lane * 4],     accA.x, accA.y);
        split_store(&sAh[rA * 136 + lane * 4 + 2], &sAl[rA * 136 + lane * 4 + 2], accA.z, accA.w);
        int rB2 = rA + 1;
        split_store(&sAh[rB2 * 136 + lane * 4],     &sAl[rB2 * 136 + lane * 4],     accB.x, accB.y);
        split_store(&sAh[rB2 * 136 + lane * 4 + 2], &sAl[rB2 * 136 + lane * 4 + 2], accB.z, accB.w);
    }

    float acc4[2][8][4];
    #pragma unroll
    for (int i = 0; i < 2; i++)
        #pragma unroll
        for (int j = 0; j < 8; j++)
            #pragma unroll
            for (int k = 0; k < 4; k++) acc4[i][j][k] = 0.0f;

    auto gemm_chunk = [&](int kt, int buf) {
        #pragma unroll
        for (int ksl = 0; ksl < 32; ksl += 16) {
            int ks = kt * 32 + ksl;
            uint32_t ah[2][4], al[2][4];
            #pragma unroll
            for (int mt = 0; mt < 2; mt++) {
                int r = warp_m * 32 + mt * 16 + (lane & 15);
                int c = ks + (lane >> 4) * 8;
                ldsm4(ah[mt][0], ah[mt][1], ah[mt][2], ah[mt][3], sptr(sAh + r * 136 + c));
                ldsm4(al[mt][0], al[mt][1], al[mt][2], al[mt][3], sptr(sAl + r * 136 + c));
            }
            #pragma unroll
            for (int np = 0; np < 4; np++) {
                int kk = ksl + (lane & 7) + ((lane >> 3) & 1) * 8;
                int cc = warp_n * 64 + np * 16 + (lane >> 4) * 8;
                uint32_t bh[4], bl[4];
                ldsm4t(bh[0], bh[1], bh[2], bh[3], sptr(sBh + buf * 4352 + kk * 136 + cc));
                ldsm4t(bl[0], bl[1], bl[2], bl[3], sptr(sBl + buf * 4352 + kk * 136 + cc));
                #pragma unroll
                for (int mt = 0; mt < 2; mt++) {
                    #pragma unroll
                    for (int sub = 0; sub < 2; sub++) {
                        float* c0 = acc4[mt][np * 2 + sub];
                        mma16816(c0, ah[mt], bh[sub * 2], bh[sub * 2 + 1]);
                        mma16816(c0, ah[mt], bl[sub * 2], bl[sub * 2 + 1]);
                        mma16816(c0, al[mt], bh[sub * 2], bh[sub * 2 + 1]);
                    }
                }
            }
        }
    };

    // -------- stage 1 --------
    #pragma unroll
    for (int kt = 0; kt < 4; kt++) {
        if (kt == 3) cpwait<0>(); else cpwait<1>();
        __syncthreads();
        gemm_chunk(kt, kt & 1);
        __syncthreads();
        if (kt + 2 < 4) { load_w(W1h, W1l, kt + 2, kt & 1); cpcommit(); }
    }

    load_w(W2h, W2l, 0, 0); cpcommit();
    load_w(W2h, W2l, 1, 1); cpcommit();

    // stage-1 epilogue: bias1 + vg mask + relu -> restage into sA (split)
    #pragma unroll
    for (int mt = 0; mt < 2; mt++) {
        int rA = warp_m * 32 + mt * 16 + (lane >> 2);
        int rB = rA + 8;
        int gA = row0 + rA, gB = row0 + rB;
        float mA = (cnt[gA] > 0) ? 1.0f : 0.0f;
        float mB = (cnt[gB] > 0) ? 1.0f : 0.0f;
        const float* vA = vg + (size_t)(gA >> 9) * HD;
        const float* vB = vg + (size_t)(gB >> 9) * HD;
        #pragma unroll
        for (int nt = 0; nt < 8; nt++) {
            int col = warp_n * 64 + nt * 8 + (lane & 3) * 2;
            float b0 = bias1[col], b1 = bias1[col + 1];
            float v0 = fmaxf(acc4[mt][nt][0] + b0 + mA * vA[col],     0.f);
            float v1 = fmaxf(acc4[mt][nt][1] + b1 + mA * vA[col + 1], 0.f);
            float v2 = fmaxf(acc4[mt][nt][2] + b0 + mB * vB[col],     0.f);
            float v3 = fmaxf(acc4[mt][nt][3] + b1 + mB * vB[col + 1], 0.f);
            split_store(&sAh[rA * 136 + col], &sAl[rA * 136 + col], v0, v1);
            split_store(&sAh[rB * 136 + col], &sAl[rB * 136 + col], v2, v3);
            acc4[mt][nt][0] = 0.f; acc4[mt][nt][1] = 0.f;
            acc4[mt][nt][2] = 0.f; acc4[mt][nt][3] = 0.f;
        }
    }

    // -------- stage 2 --------
    #pragma unroll
    for (int kt = 0; kt < 4; kt++) {
        if (kt == 3) cpwait<0>(); else cpwait<1>();
        __syncthreads();
        gemm_chunk(kt, kt & 1);
        __syncthreads();
        if (kt + 2 < 4) { load_w(W2h, W2l, kt + 2, kt & 1); cpcommit(); }
    }

    // stage-2 epilogue: bias2, optional store + ssq, column partial sums
    float ps0[8], ps1[8];
    #pragma unroll
    for (int nt = 0; nt < 8; nt++) { ps0[nt] = 0.f; ps1[nt] = 0.f; }
    #pragma unroll
    for (int mt = 0; mt < 2; mt++) {
        int rA = warp_m * 32 + mt * 16 + (lane >> 2);
        int rB = rA + 8;
        float ssA = 0.f, ssB = 0.f;
        #pragma unroll
        for (int nt = 0; nt < 8; nt++) {
            int col = warp_n * 64 + nt * 8 + (lane & 3) * 2;
            float b0 = bias2[col], b1 = bias2[col + 1];
            float v0 = acc4[mt][nt][0] + b0;
            float v1 = acc4[mt][nt][1] + b1;
            float v2 = acc4[mt][nt][2] + b0;
            float v3 = acc4[mt][nt][3] + b1;
            ps0[nt] += v0 + v2;
            ps1[nt] += v1 + v3;
            if (Cout) {
                *(float2*)(Cout + (size_t)(row0 + rA) * 128 + col) = make_float2(v0, v1);
                *(float2*)(Cout + (size_t)(row0 + rB) * 128 + col) = make_float2(v2, v3);
                ssA += v0 * v0 + v1 * v1;
                ssB += v2 * v2 + v3 * v3;
            }
        }
        if (Cout) {
            ssA = quadsum(ssA); ssB = quadsum(ssB);
            if ((lane & 3) == 0) {
                sred[warp_n * 128 + rA] = ssA;
                sred[warp_n * 128 + rB] = ssB;
            }
        }
    }
    #pragma unroll
    for (int nt = 0; nt < 8; nt++) {
        #pragma unroll
        for (int o = 4; o < 32; o <<= 1) {
            ps0[nt] += __shfl_xor_sync(0xffffffffu, ps0[nt], o);
            ps1[nt] += __shfl_xor_sync(0xffffffffu, ps1[nt], o);
        }
    }
    float* scol = sred + 256;     // [4][128]
    if (lane < 4) {
        #pragma unroll
        for (int nt = 0; nt < 8; nt++) {
            int col = warp_n * 64 + nt * 8 + lane * 2;
            scol[warp_m * 128 + col]     = ps0[nt];
            scol[warp_m * 128 + col + 1] = ps1[nt];
        }
    }
    __syncthreads();
    if (tid < 128) {
        gpart[(size_t)blockIdx.x * 128 + tid] =
            scol[tid] + scol[128 + tid] + scol[256 + tid] + scol[384 + tid];
        if (Cout) ssq_out[row0 + tid] = sred[tid] + sred[128 + tid];
    }
}

// ---------------- fused query layer (256 thr, 8 warps x 1 node-pair, fixed-offset softmax) ----------------
__global__ __launch_bounds__(256) void qlayer(
    const float* __restrict__ hq, const float* __restrict__ ssq_in,
    const int* __restrict__ csr_src, const int* __restrict__ start,
    const int* __restrict__ cnt,
    const float* __restrict__ betas, int l,
    const float* __restrict__ W1bot,
    float* __restrict__ hq_out, float* __restrict__ ssq_out,
    float* __restrict__ ssqa, float* __restrict__ vgout,
    const float* __restrict__ ssqg, float* __restrict__ invg)
{
    __shared__ float rows[NQPG][132];
    __shared__ float aggs[NQPG][132];
    __shared__ float sssq[NQPG];
    __shared__ float spart[2][HD];
    __shared__ float srow[HD];
    __shared__ float st[HD];
    int g = blockIdx.x, tid = threadIdx.x;
    int wid = tid >> 5, lane = tid & 31;
    int nodebase = g * NQPG;

    // stage input rows (2 per warp) + ssq
    {
        int j = wid * 2;
        *(float4*)&rows[j][lane * 4] =
            *(const float4*)(hq + (size_t)(nodebase + j) * HD + lane * 4);
        *(float4*)&rows[j + 1][lane * 4] =
            *(const float4*)(hq + (size_t)(nodebase + j + 1) * HD + lane * 4);
    }
    if (tid < NQPG) sssq[tid] = ssq_in[nodebase + tid];
    __syncthreads();

    float beta = betas[l];
    float Cb = fabsf(beta);
    {
        int rA = wid * 2, rB = rA + 1;
        int cA = cnt[nodebase + rA], cB = cnt[nodebase + rB];
        float4 accA = make_float4(0.f, 0.f, 0.f, 0.f);
        float4 accB = make_float4(0.f, 0.f, 0.f, 0.f);
        if (cA > 0 || cB > 0) {
            float4 hdA = *(const float4*)&rows[rA][lane * 4];
            float4 hdB = *(const float4*)&rows[rB][lane * 4];
            float invdA = rsqrtf(sssq[rA] + 1e-24f);
            float invdB = rsqrtf(sssq[rB] + 1e-24f);
            int sA0 = start[nodebase + rA], sB0 = start[nodebase + rB];
            float denA = 0.f, denB = 0.f;
            int jA = 0, jB = 0;
            while (jA < cA || jB < cB) {
                int vA = cA - jA, vB = cB - jB;
                float4 rwA[4], rwB[4]; float eA[4], eB[4];
                #pragma unroll
                for (int j = 0; j < 4; j++) {
                    if (j < vA) {
                        int s = csr_src[sA0 + jA + j] - nodebase;
                        rwA[j] = *(const float4*)&rows[s][lane * 4];
                        eA[j] = sssq[s];
                    } else { rwA[j] = make_float4(0.f, 0.f, 0.f, 0.f); eA[j] = 1.f; }
                    if (j < vB) {
                        int s = csr_src[sB0 + jB + j] - nodebase;
                        rwB[j] = *(const float4*)&rows[s][lane * 4];
                        eB[j] = sssq[s];
                    } else { rwB[j] = make_float4(0.f, 0.f, 0.f, 0.f); eB[j] = 1.f; }
                }
                float dA[4], dB[4];
                #pragma unroll
                for (int j = 0; j < 4; j++) {
                    dA[j] = rwA[j].x * hdA.x + rwA[j].y * hdA.y + rwA[j].z * hdA.z + rwA[j].w * hdA.w;
                    dB[j] = rwB[j].x * hdB.x + rwB[j].y * hdB.y + rwB[j].z * hdB.z + rwB[j].w * hdB.w;
                }
                #pragma unroll
                for (int o = 16; o; o >>= 1) {
                    #pragma unroll
                    for (int j = 0; j < 4; j++) {
                        dA[j] += __shfl_xor_sync(0xffffffffu, dA[j], o);
                        dB[j] += __shfl_xor_sync(0xffffffffu, dB[j], o);
                    }
                }
                #pragma unroll
                for (int j = 0; j < 4; j++) {
                    float evA = (j < vA) ? beta * dA[j] * rsqrtf(eA[j] + 1e-24f) * invdA - Cb
                                         : -CUDART_INF_F;
                    float ppA = __expf(evA);
                    denA += ppA;
                    accA.x += ppA * rwA[j].x; accA.y += ppA * rwA[j].y;
                    accA.z += ppA * rwA[j].z; accA.w += ppA * rwA[j].w;
                    float evB = (j < vB) ? beta * dB[j] * rsqrtf(eB[j] + 1e-24f) * invdB - Cb
                                         : -CUDART_INF_F;
                    float ppB = __expf(evB);
                    denB += ppB;
                    accB.x += ppB * rwB[j].x; accB.y += ppB * rwB[j].y;
                    accB.z += ppB * rwB[j].z; accB.w += ppB * rwB[j].w;
                }
                jA += 4; jB += 4;
            }
            if (cA > 0) {
                float rr = 1.0f / fmaxf(denA, 1e-24f);
                accA.x *= rr; accA.y *= rr; accA.z *= rr; accA.w *= rr;
            }
            if (cB > 0) {
                float rr = 1.0f / fmaxf(denB, 1e-24f);
                accB.x *= rr; accB.y *= rr; accB.z *= rr; accB.w *= rr;
            }
        }
        *(float4*)&aggs[rA][lane * 4] = accA;
        *(float4*)&aggs[rB][lane * 4] = accB;
        *(float4*)(hq_out + (size_t)(nodebase + rA) * HD + lane * 4) = accA;
        *(float4*)(hq_out + (size_t)(nodebase + rB) * HD + lane * 4) = accB;
        float sA = accA.x * accA.x + accA.y * accA.y + accA.z * accA.z + accA.w * accA.w;
        float sB = accB.x * accB.x + accB.y * accB.y + accB.z * accB.z + accB.w * accB.w;
        #pragma unroll
        for (int o = 16; o; o >>= 1) {
            sA += __shfl_xor_sync(0xffffffffu, sA, o);
            sB += __shfl_xor_sync(0xffffffffu, sB, o);
        }
        if (lane == 0) {
            ssq_out[nodebase + rA] = sA;
            ssq_out[nodebase + rB] = sB;
        }
    }
    __syncthreads();

    // pool (2-way split) + ssqa
    int col = tid & 127, part = tid >> 7;
    {
        float a = 0.0f;
        #pragma unroll
        for (int j = 0; j < 8; j++) a += aggs[part * 8 + j][col];
        spart[part][col] = a;
    }
    __syncthreads();
    if (tid < 128) {
        float s = spart[0][tid] + spart[1][tid];
        srow[tid] = s;
        st[tid] = s * s;
    }
    __syncthreads();
    #pragma unroll
    for (int o = 64; o; o >>= 1) {
        if (tid < o) st[tid] += st[tid + o];
        __syncthreads();
    }
    float exv = st[0];
    if (tid == 0) ssqa[g] = exv;

    // vg = aggr @ W1bot (2-way k split)
    {
        float v = 0.0f;
        #pragma unroll 8
        for (int k = 0; k < 64; k++)
            v += srow[part * 64 + k] * W1bot[(part * 64 + k) * HD + col];
        spart[part][col] = v;
    }
    __syncthreads();
    if (tid < 128) vgout[g * HD + tid] = spart[0][tid] + spart[1][tid];

    // precompute inv for this block's DATA graph nodes
    #pragma unroll
    for (int j = 0; j < NPG / 256; j++) {
        int n = g * NPG + j * 256 + tid;
        invg[n] = rsqrtf(ssqg[n] + exv + 1e-24f);
    }
}

// ---------------- final predictor from block partials ----------------
__global__ void pool_pred2(const float* __restrict__ gpart, const float* __restrict__ Wp1,
                           const float* __restrict__ bp1, const float* __restrict__ Wp2,
                           const float* __restrict__ bp2, float* __restrict__ y)
{
    __shared__ float srow[HD];
    __shared__ float st[HD];
    int g = blockIdx.x, t = threadIdx.x;   // 128 threads; 4 blocks per graph
    srow[t] = gpart[(size_t)(4 * g) * 128 + t] + gpart[(size_t)(4 * g + 1) * 128 + t]
            + gpart[(size_t)(4 * g + 2) * 128 + t] + gpart[(size_t)(4 * g + 3) * 128 + t];
    __syncthreads();
    float a = 0.0f;
    #pragma unroll 8
    for (int k = 0; k < HD; k++) a += srow[k] * Wp1[k * HD + t];
    st[t] = fmaxf(a + bp1[t], 0.0f) * Wp2[t];
    __syncthreads();
    #pragma unroll
    for (int o = 64; o; o >>= 1) {
        if (t < o) st[t] += st[t + o];
        __syncthreads();
    }
    if (t == 0) y[g] = st[0] + bp2[0];
}

// ---------------- launch ----------------
extern "C" void kernel_launch(void* const* d_in, const int* in_sizes, int n_in,
                              void* d_out, int out_size)
{
    const float* X     = (const float*)d_in[0];
    const float* Xq    = (const float*)d_in[1];
    const int*   g_src = (const int*)d_in[2];
    const int*   g_dst = (const int*)d_in[3];
    const int*   q_src = (const int*)d_in[5];
    const int*   q_dst = (const int*)d_in[6];
    const float* Wg    = (const float*)d_in[8];
    const float* bg    = (const float*)d_in[9];
    const float* Wq    = (const float*)d_in[10];
    const float* bq    = (const float*)d_in[11];
    const float* betas_g = (const float*)d_in[12];
    const float* betas_q = (const float*)d_in[13];
    const float* W1r   = (const float*)d_in[14];
    const float* b1r   = (const float*)d_in[15];
    const float* W2r   = (const float*)d_in[16];
    const float* b2r   = (const float*)d_in[17];
    const float* Wp1   = (const float*)d_in[18];
    const float* bp1   = (const float*)d_in[19];
    const float* Wp2   = (const float*)d_in[20];
    const float* bp2   = (const float*)d_in[21];
    float* y = (float*)d_out;

    float *hgA, *hgB, *hqA, *hqB, *ssqgA, *ssqgB, *ssqqA, *ssqqB, *invg;
    float *ssqa0, *ssqa1, *vg0, *vg1, *part;
    bf16 *Wh, *Wl;
    int *csrg, *startg, *cntg, *csrq, *startq, *cntq;
    cudaGetSymbolAddress((void**)&hgA, d_hgA);
    cudaGetSymbolAddress((void**)&hgB, d_hgB);
    cudaGetSymbolAddress((void**)&hqA, d_hqA);
    cudaGetSymbolAddress((void**)&hqB, d_hqB);
    cudaGetSymbolAddress((void**)&ssqgA, d_ssqgA);
    cudaGetSymbolAddress((void**)&ssqgB, d_ssqgB);
    cudaGetSymbolAddress((void**)&ssqqA, d_ssqqA);
    cudaGetSymbolAddress((void**)&ssqqB, d_ssqqB);
    cudaGetSymbolAddress((void**)&invg, d_invg);
    cudaGetSymbolAddress((void**)&ssqa0, d_ssqa0);
    cudaGetSymbolAddress((void**)&ssqa1, d_ssqa1);
    cudaGetSymbolAddress((void**)&vg0, d_vg0);
    cudaGetSymbolAddress((void**)&vg1, d_vg1);
    cudaGetSymbolAddress((void**)&part, d_part);
    cudaGetSymbolAddress((void**)&Wh, d_Wh);
    cudaGetSymbolAddress((void**)&Wl, d_Wl);
    cudaGetSymbolAddress((void**)&csrg, d_csrg);
    cudaGetSymbolAddress((void**)&startg, d_startg);
    cudaGetSymbolAddress((void**)&cntg, d_cntg);
    cudaGetSymbolAddress((void**)&csrq, d_csrq);
    cudaGetSymbolAddress((void**)&startq, d_startq);
    cudaGetSymbolAddress((void**)&cntq, d_cntq);

    const int SM_IN  = 2 * (128 * 72 * 2) + 2 * (64 * 136 * 2) + 256 * 4;
    const int SM_MLP = 2 * (128 * 136 * 2) + 2 * (2 * 32 * 136 * 2) + (256 + 512) * 4;
    cudaFuncSetAttribute(gemm_in,   cudaFuncAttributeMaxDynamicSharedMemorySize, SM_IN);
    cudaFuncSetAttribute(mlp_fused, cudaFuncAttributeMaxDynamicSharedMemorySize, SM_MLP);

    // setup: data-graph CSR + (query CSR | weight split)
    build_csr3<NPG, EGE / NB, 16><<<NB, 512>>>(g_src, g_dst, csrg, startg, cntg);
    const int WS_BLOCKS = (WTOT / 4 + 127) / 128;    // 160
    setup_q_ws<<<NB + WS_BLOCKS, 128>>>(q_src, q_dst, csrq, startq, cntq,
                                        Wg, Wq, W1r, W2r, Wh, Wl);

    // merged input projections (data + query)
    gemm_in<<<NGN / 128 + NQN / 128, 256, SM_IN>>>(
        X,  Wh + OFF_WG, Wl + OFF_WG, bg, hgA, ssqgA,
        Xq, Wh + OFF_WQ, Wl + OFF_WQ, bq, hqA, ssqqA,
        NGN / 128);

    // layer 0
    qlayer<<<NB, 256>>>(hqA, ssqqA, csrq, startq, cntq, betas_q, 0,
                        W1r + 0 * 2 * HD * HD + HD * HD, hqB, ssqqB, ssqa0, vg0,
                        ssqgA, invg);
    mlp_fused<<<NGN / 128, 256, SM_MLP>>>(hgA, invg, csrg, startg, cntg,
                                          betas_g, 0, ssqa0,
                                          Wh + OFF_W1(0), Wl + OFF_W1(0),
                                          Wh + OFF_W2(0), Wl + OFF_W2(0),
                                          b1r, b2r, vg0, hgB, ssqgB, part);

    // layer 1
    qlayer<<<NB, 256>>>(hqB, ssqqB, csrq, startq, cntq, betas_q, 1,
                        W1r + (size_t)1 * 2 * HD * HD + HD * HD, hqA, ssqqA, ssqa1, vg1,
                        ssqgB, invg);
    mlp_fused<<<NGN / 128, 256, SM_MLP>>>(hgB, ssqgB == nullptr ? nullptr : invg, csrg, startg, cntg,
                                          betas_g, 1, ssqa1,
                                          Wh + OFF_W1(1), Wl + OFF_W1(1),
                                          Wh + OFF_W2(1), Wl + OFF_W2(1),
                                          b1r + HD, b2r + HD, vg1,
                                          nullptr, nullptr, part);

    pool_pred2<<<NB, 128>>>(part, Wp1, bp1, Wp2, bp2, y);
}